// round 13
// baseline (speedup 1.0000x reference)
#include <cuda_runtime.h>
#include <cuda_fp16.h>
#include <cstdint>

#define B_   2
#define S_   2048
#define D_   2048
#define H_   16
#define KVH_ 8
#define HD_  128

// ---------------- scratch (no allocations allowed) ----------------
__device__ __half g_xh   [B_ * S_ * D_];
__device__ __half g_qh   [B_ * S_ * D_];
__device__ __half g_kh   [B_ * S_ * KVH_ * HD_];
__device__ __half g_vt   [(KVH_ * HD_) * (B_ * S_)];   // V^T  [1024][4096]
__device__ __half g_oh   [B_ * S_ * D_];
__device__ __half g_wqkvt[(D_ + 2 * KVH_ * HD_) * D_]; // [4096][2048]: wq^T|wk^T|wv^T
__device__ __half g_wot  [D_ * D_];

// ---------------- helpers ----------------
__device__ __forceinline__ void cpa16(uint32_t dst, const void* src) {
    asm volatile("cp.async.cg.shared.global [%0], [%1], 16;" :: "r"(dst), "l"(src));
}
__device__ __forceinline__ void cpa_commit() { asm volatile("cp.async.commit_group;"); }
__device__ __forceinline__ void cpa_wait0()  { asm volatile("cp.async.wait_group 0;"); }
__device__ __forceinline__ void cpa_wait1()  { asm volatile("cp.async.wait_group 1;"); }
__device__ __forceinline__ void mma_f16(float c[4], const uint32_t a[4], const uint32_t b[2]) {
    asm volatile(
        "mma.sync.aligned.m16n8k16.row.col.f32.f16.f16.f32 "
        "{%0,%1,%2,%3}, {%4,%5,%6,%7}, {%8,%9}, {%0,%1,%2,%3};"
        : "+f"(c[0]), "+f"(c[1]), "+f"(c[2]), "+f"(c[3])
        : "r"(a[0]), "r"(a[1]), "r"(a[2]), "r"(a[3]), "r"(b[0]), "r"(b[1]));
}
__device__ __forceinline__ void ldsm_x4(uint32_t& r0, uint32_t& r1, uint32_t& r2, uint32_t& r3,
                                        uint32_t addr) {
    asm volatile("ldmatrix.sync.aligned.m8n8.x4.shared.b16 {%0,%1,%2,%3}, [%4];"
                 : "=r"(r0), "=r"(r1), "=r"(r2), "=r"(r3) : "r"(addr));
}
__device__ __forceinline__ uint32_t smem_u32(const void* p) {
    return (uint32_t)__cvta_generic_to_shared(p);
}
__device__ __forceinline__ uint32_t h2u(__half2 h) { return *(uint32_t*)&h; }

// =================================================================
// Prepass
// =================================================================
__global__ void f2h_kernel(const float* __restrict__ in, __half* __restrict__ out, int n4) {
    int i = blockIdx.x * blockDim.x + threadIdx.x;
    if (i >= n4) return;
    float4 v = ((const float4*)in)[i];
    __half2 a = __floats2half2_rn(v.x, v.y);
    __half2 b = __floats2half2_rn(v.z, v.w);
    ((uint2*)out)[i] = make_uint2(h2u(a), h2u(b));
}

__global__ void trans_all(const float* __restrict__ wq, const float* __restrict__ wk,
                          const float* __restrict__ wv, const float* __restrict__ wo,
                          __half* __restrict__ wqkvt, __half* __restrict__ wot) {
    __shared__ float tb[32][33];
    int id = blockIdx.x;
    const float* W;
    __half* WT;
    int N;
    if (id < 4096)      { W = wq; WT = wqkvt;                          N = 2048; }
    else if (id < 6144) { W = wk; WT = wqkvt + 2048 * 2048; id -= 4096; N = 1024; }
    else if (id < 8192) { W = wv; WT = wqkvt + 3072 * 2048; id -= 6144; N = 1024; }
    else                { W = wo; WT = wot;                 id -= 8192; N = 2048; }
    int nb = N / 32;
    int n0 = (id % nb) * 32, k0 = (id / nb) * 32;
    int tx = threadIdx.x, ty = threadIdx.y;
    #pragma unroll
    for (int i = 0; i < 4; ++i)
        tb[ty + i * 8][tx] = W[(size_t)(k0 + ty + i * 8) * N + n0 + tx];
    __syncthreads();
    #pragma unroll
    for (int i = 0; i < 4; ++i)
        WT[(size_t)(n0 + ty + i * 8) * 2048 + k0 + tx] = __float2half_rn(tb[tx][ty + i * 8]);
}

__global__ void nop_kernel() {}

// =================================================================
// GEMM mainloop v5: 128x128 CTA, 4 warps (2x2 of 64x64), BK=64,
// 3-stage cp.async, ONE __syncthreads per k-tile, ldmatrix loads,
// 2 CTAs/SM. smem: A @0/16K/32K ; B @48K/64K/80K. 96KB/CTA.
// Iter order: wait(t) -> sync -> prefetch(t+2) -> compute(t).
// =================================================================
#define HG3_SMEM 98304

#define GEMM_STAGE(A_, Bt_, Kdim, c)                                                    \
    do {                                                                                \
        uint32_t ao = ((c) % 3) * 16384u;                                               \
        uint32_t bo = 49152u + ((c) % 3) * 16384u;                                      \
        const __half* ap = aBase + (size_t)(c) * 64;                                    \
        const __half* bp = bBase + (size_t)(c) * 64;                                    \
        _Pragma("unroll")                                                               \
        for (int i = 0; i < 8; ++i) cpa16(sbase + ao + sD0 + i * 2048u, ap + (size_t)i * 16 * (Kdim)); \
        _Pragma("unroll")                                                               \
        for (int i = 0; i < 8; ++i) cpa16(sbase + bo + sD0 + i * 2048u, bp + (size_t)i * 16 * (Kdim)); \
        cpa_commit();                                                                   \
    } while (0)

#define GEMM3_MAIN(A_, Bt_, Kdim)                                                       \
    extern __shared__ char smh[];                                                       \
    const uint32_t sbase = smem_u32(smh);                                               \
    const int tid  = threadIdx.x, lane = tid & 31, w = tid >> 5;                        \
    const int g    = lane >> 2, t4 = lane & 3;                                          \
    const int wm   = w >> 1, wn = w & 1;                                                \
    const int bm   = blockIdx.y << 7, bn = blockIdx.x << 7;                             \
    const int sr   = tid >> 3, sc = tid & 7;                                            \
    const __half* aBase = A_ + (size_t)(bm + sr) * (Kdim) + sc * 8;                     \
    const __half* bBase = Bt_ + (size_t)(bn + sr) * (Kdim) + sc * 8;                    \
    const uint32_t sD0 = (uint32_t)(sr * 128 + ((sc ^ (sr & 7)) << 4));                 \
    const int arow0 = wm * 64 + ((lane >> 3) & 1) * 8 + (lane & 7);                     \
    const int achq  = lane >> 4;                                                        \
    const int brow0 = wn * 64 + (lane >> 4) * 8 + (lane & 7);                           \
    const int bchq  = (lane >> 3) & 1;                                                  \
    float acc[4][8][4];                                                                 \
    _Pragma("unroll")                                                                   \
    for (int i = 0; i < 4; ++i)                                                         \
        _Pragma("unroll")                                                               \
        for (int j = 0; j < 8; ++j)                                                     \
            _Pragma("unroll")                                                           \
            for (int r = 0; r < 4; ++r) acc[i][j][r] = 0.f;                             \
    const int ktiles = (Kdim) >> 6;                                                     \
    GEMM_STAGE(A_, Bt_, Kdim, 0);                                                       \
    GEMM_STAGE(A_, Bt_, Kdim, 1);                                                       \
    for (int tt = 0; tt < ktiles; ++tt) {                                               \
        if (tt + 1 < ktiles) cpa_wait1(); else cpa_wait0();                             \
        __syncthreads();                                                                \
        if (tt + 2 < ktiles) GEMM_STAGE(A_, Bt_, Kdim, tt + 2);                         \
        const uint32_t sA = sbase + (tt % 3) * 16384u;                                  \
        const uint32_t sB = sbase + 49152u + (tt % 3) * 16384u;                         \
        _Pragma("unroll")                                                               \
        for (int s = 0; s < 4; ++s) {                                                   \
            uint32_t a[4][4], b[8][2];                                                  \
            _Pragma("unroll")                                                           \
            for (int i = 0; i < 4; ++i) {                                               \
                int row = arow0 + i * 16;                                               \
                int ch  = (2 * s + achq) ^ (row & 7);                                   \
                ldsm_x4(a[i][0], a[i][1], a[i][2], a[i][3], sA + row * 128 + (ch << 4)); \
            }                                                                           \
            _Pragma("unroll")                                                           \
            for (int p = 0; p < 4; ++p) {                                               \
                int row = brow0 + p * 16;                                               \
                int ch  = (2 * s + bchq) ^ (row & 7);                                   \
                ldsm_x4(b[2 * p][0], b[2 * p][1], b[2 * p + 1][0], b[2 * p + 1][1],     \
                        sB + row * 128 + (ch << 4));                                    \
            }                                                                           \
            _Pragma("unroll")                                                           \
            for (int i = 0; i < 4; ++i)                                                 \
                _Pragma("unroll")                                                       \
                for (int j = 0; j < 8; ++j)                                             \
                    mma_f16(acc[i][j], a[i], b[j]);                                     \
        }                                                                               \
    }

// =================================================================
// Fused QKV projection + RoPE epilogue.
// =================================================================
__global__ __launch_bounds__(128, 2)
void hgemm_qkv(const __half* __restrict__ A, const __half* __restrict__ Bt,
               const float* __restrict__ cs, const float* __restrict__ sn,
               __half* __restrict__ Qo, __half* __restrict__ Ko, __half* __restrict__ Vt) {
    GEMM3_MAIN(A, Bt, D_)

    const float SCALE = 0.08838834764831845f;   // 1/sqrt(128)
    const int cc = t4 * 2;
    if (bn < D_) {
        #pragma unroll
        for (int i = 0; i < 4; ++i)
            #pragma unroll
            for (int j = 0; j < 8; ++j) {
                int row = bm + wm * 64 + i * 16 + g;
                int col = bn + wn * 64 + j * 8 + cc;
                int dd  = (col & 127) >> 1;
                int s_lo = row & (S_ - 1), s_hi = (row + 8) & (S_ - 1);
                float c0 = cs[s_lo * 64 + dd], si0 = sn[s_lo * 64 + dd];
                float c1 = cs[s_hi * 64 + dd], si1 = sn[s_hi * 64 + dd];
                float r0 = (acc[i][j][0] * c0 - acc[i][j][1] * si0) * SCALE;
                float r1 = (acc[i][j][0] * si0 + acc[i][j][1] * c0) * SCALE;
                float r2 = (acc[i][j][2] * c1 - acc[i][j][3] * si1) * SCALE;
                float r3 = (acc[i][j][2] * si1 + acc[i][j][3] * c1) * SCALE;
                *(__half2*)(Qo + (size_t)row * D_ + col)       = __floats2half2_rn(r0, r1);
                *(__half2*)(Qo + (size_t)(row + 8) * D_ + col) = __floats2half2_rn(r2, r3);
            }
    } else if (bn < D_ + KVH_ * HD_) {
        #pragma unroll
        for (int i = 0; i < 4; ++i)
            #pragma unroll
            for (int j = 0; j < 8; ++j) {
                int row = bm + wm * 64 + i * 16 + g;
                int col = bn - D_ + wn * 64 + j * 8 + cc;
                int dd  = (col & 127) >> 1;
                int s_lo = row & (S_ - 1), s_hi = (row + 8) & (S_ - 1);
                float c0 = cs[s_lo * 64 + dd], si0 = sn[s_lo * 64 + dd];
                float c1 = cs[s_hi * 64 + dd], si1 = sn[s_hi * 64 + dd];
                float r0 = acc[i][j][0] * c0 - acc[i][j][1] * si0;
                float r1 = acc[i][j][0] * si0 + acc[i][j][1] * c0;
                float r2 = acc[i][j][2] * c1 - acc[i][j][3] * si1;
                float r3 = acc[i][j][2] * si1 + acc[i][j][3] * c1;
                *(__half2*)(Ko + (size_t)row * (KVH_ * HD_) + col)       = __floats2half2_rn(r0, r1);
                *(__half2*)(Ko + (size_t)(row + 8) * (KVH_ * HD_) + col) = __floats2half2_rn(r2, r3);
            }
    } else {
        const int M = B_ * S_;
        #pragma unroll
        for (int i = 0; i < 4; ++i)
            #pragma unroll
            for (int j = 0; j < 8; ++j) {
                int row = bm + wm * 64 + i * 16 + g;
                int col = bn - (D_ + KVH_ * HD_) + wn * 64 + j * 8 + cc;
                Vt[(size_t)col * M + row]           = __float2half_rn(acc[i][j][0]);
                Vt[(size_t)(col + 1) * M + row]     = __float2half_rn(acc[i][j][1]);
                Vt[(size_t)col * M + row + 8]       = __float2half_rn(acc[i][j][2]);
                Vt[(size_t)(col + 1) * M + row + 8] = __float2half_rn(acc[i][j][3]);
            }
    }
}

// =================================================================
// O-projection GEMM: half in, fp32 out.
// =================================================================
__global__ __launch_bounds__(128, 2)
void hgemm_out(const __half* __restrict__ A, const __half* __restrict__ Bt,
               float* __restrict__ Cf, int N) {
    GEMM3_MAIN(A, Bt, D_)
    const int cc = t4 * 2;
    #pragma unroll
    for (int i = 0; i < 4; ++i)
        #pragma unroll
        for (int j = 0; j < 8; ++j) {
            int row = bm + wm * 64 + i * 16 + g;
            int col = bn + wn * 64 + j * 8 + cc;
            *(float2*)(Cf + (size_t)row * N + col)       = make_float2(acc[i][j][0], acc[i][j][1]);
            *(float2*)(Cf + (size_t)(row + 8) * N + col) = make_float2(acc[i][j][2], acc[i][j][3]);
        }
}

// =================================================================
// FP16 flash attention: 64 Q-rows per CTA, 128 threads (4 warps),
// 3-stage cp.async, ONE __syncthreads per k-tile, 2 CTAs/SM.
// smem: 3 stages x (K 16KB + V 16KB) = 96KB.
// =================================================================
#define ATTN_SMEM 98304

__global__ __launch_bounds__(128, 2)
void attn_h(const __half* __restrict__ Q, const __half* __restrict__ Kg,
            const __half* __restrict__ Vt, __half* __restrict__ O) {
    extern __shared__ char smc[];
    const uint32_t sbase = smem_u32(smc);
    const int tid = threadIdx.x, lane = tid & 31, w = tid >> 5;
    const int g = lane >> 2, t = lane & 3;

    const int qtile = gridDim.x - 1 - blockIdx.x;   // heavy CTAs first
    const int h = blockIdx.y, b = blockIdx.z;
    const int q0 = qtile * 64, kh = h >> 1;
    const int r_lo = w * 16 + g, r_hi = r_lo + 8;

    const int lrow = ((lane >> 4) << 3) + (lane & 7);
    const int lchq = (lane >> 3) & 1;

    const __half* qlo = Q + (size_t)(b * S_ + q0 + r_lo) * D_ + h * HD_;
    const __half* qhi = Q + (size_t)(b * S_ + q0 + r_hi) * D_ + h * HD_;
    uint32_t qa[8][4];
    #pragma unroll
    for (int s = 0; s < 8; ++s) {
        qa[s][0] = *(const uint32_t*)(qlo + s * 16 + 2 * t);
        qa[s][1] = *(const uint32_t*)(qhi + s * 16 + 2 * t);
        qa[s][2] = *(const uint32_t*)(qlo + s * 16 + 2 * t + 8);
        qa[s][3] = *(const uint32_t*)(qhi + s * 16 + 2 * t + 8);
    }

    const __half* kbp = Kg + (size_t)b * S_ * (KVH_ * HD_) + kh * HD_;
    const __half* vtp = Vt + (size_t)(kh * HD_) * (B_ * S_) + b * S_;

    float m_lo = -1e30f, m_hi = -1e30f, l_lo = 0.f, l_hi = 0.f;
    float oacc[16][4];
    #pragma unroll
    for (int j = 0; j < 16; ++j)
        #pragma unroll
        for (int r = 0; r < 4; ++r) oacc[j][r] = 0.f;

    const int nkt = qtile + 1;

    // K: 64 rows x 16 chunks (256B rows); V: 128 rows x 8 chunks (128B rows)
#define PREF(ktp) do {                                                             \
        int k0p = (ktp) * 64;                                                      \
        uint32_t kb2 = sbase + ((ktp) % 3) * 32768u;                               \
        uint32_t vb2 = kb2 + 16384u;                                               \
        _Pragma("unroll")                                                          \
        for (int i = 0; i < 8; ++i) {                                              \
            int idx = tid + i * 128; int r = idx >> 4, c = idx & 15;               \
            int cp = (c & 8) | ((c ^ (r & 7)) & 7);                                \
            cpa16(kb2 + (uint32_t)(r * 256 + cp * 16),                             \
                  kbp + (size_t)(k0p + r) * (KVH_ * HD_) + c * 8);                 \
        }                                                                          \
        _Pragma("unroll")                                                          \
        for (int i = 0; i < 8; ++i) {                                              \
            int idx = tid + i * 128; int d = idx >> 3, c = idx & 7;                \
            int cp = c ^ (d & 7);                                                  \
            cpa16(vb2 + (uint32_t)(d * 128 + cp * 16),                             \
                  vtp + (size_t)d * (B_ * S_) + k0p + c * 8);                      \
        }                                                                          \
        cpa_commit();                                                              \
    } while (0)

    PREF(0);
    if (nkt > 1) PREF(1);

    for (int kt = 0; kt < nkt; ++kt) {
        const int k0 = kt * 64;
        if (kt + 1 < nkt) cpa_wait1(); else cpa_wait0();
        __syncthreads();
        if (kt + 2 < nkt) PREF(kt + 2);

        const uint32_t kbuf = sbase + (kt % 3) * 32768u;
        const uint32_t vbuf = kbuf + 16384u;

        // ---- S = Q K^T ----
        float sacc[8][4];
        #pragma unroll
        for (int j = 0; j < 8; ++j)
            #pragma unroll
            for (int r = 0; r < 4; ++r) sacc[j][r] = 0.f;

        #pragma unroll
        for (int s = 0; s < 8; ++s) {
            uint32_t bb[8][2];
            #pragma unroll
            for (int p = 0; p < 4; ++p) {
                int row = p * 16 + lrow;
                int ch  = 2 * s + lchq;
                int cp  = (ch & 8) | ((ch ^ (row & 7)) & 7);
                ldsm_x4(bb[2 * p][0], bb[2 * p][1], bb[2 * p + 1][0], bb[2 * p + 1][1],
                        kbuf + row * 256 + cp * 16);
            }
            #pragma unroll
            for (int j = 0; j < 8; ++j)
                mma_f16(sacc[j], qa[s], bb[j]);
        }

        // ---- causal mask (diagonal tile only) ----
        if (kt == qtile) {
            const int lim_lo = q0 + r_lo - k0;
            const int lim_hi = q0 + r_hi - k0;
            #pragma unroll
            for (int j = 0; j < 8; ++j) {
                int c0 = j * 8 + 2 * t, c1 = c0 + 1;
                if (c0 > lim_lo) sacc[j][0] = -1e30f;
                if (c1 > lim_lo) sacc[j][1] = -1e30f;
                if (c0 > lim_hi) sacc[j][2] = -1e30f;
                if (c1 > lim_hi) sacc[j][3] = -1e30f;
            }
        }

        // ---- online softmax ----
        float mv_lo = -1e30f, mv_hi = -1e30f;
        #pragma unroll
        for (int j = 0; j < 8; ++j) {
            mv_lo = fmaxf(mv_lo, fmaxf(sacc[j][0], sacc[j][1]));
            mv_hi = fmaxf(mv_hi, fmaxf(sacc[j][2], sacc[j][3]));
        }
        #pragma unroll
        for (int off = 1; off <= 2; off <<= 1) {
            mv_lo = fmaxf(mv_lo, __shfl_xor_sync(0xffffffffu, mv_lo, off));
            mv_hi = fmaxf(mv_hi, __shfl_xor_sync(0xffffffffu, mv_hi, off));
        }
        float mn_lo = fmaxf(m_lo, mv_lo);
        float mn_hi = fmaxf(m_hi, mv_hi);
        float corr_lo = __expf(m_lo - mn_lo);
        float corr_hi = __expf(m_hi - mn_hi);
        m_lo = mn_lo; m_hi = mn_hi;

        float ls_lo = 0.f, ls_hi = 0.f;
        uint32_t ph_lo[8], ph_hi[8];
        #pragma unroll
        for (int j = 0; j < 8; ++j) {
            float p0 = __expf(sacc[j][0] - mn_lo);
            float p1 = __expf(sacc[j][1] - mn_lo);
            float p2 = __expf(sacc[j][2] - mn_hi);
            float p3 = __expf(sacc[j][3] - mn_hi);
            ls_lo += p0 + p1;
            ls_hi += p2 + p3;
            ph_lo[j] = h2u(__floats2half2_rn(p0, p1));
            ph_hi[j] = h2u(__floats2half2_rn(p2, p3));
        }
        #pragma unroll
        for (int off = 1; off <= 2; off <<= 1) {
            ls_lo += __shfl_xor_sync(0xffffffffu, ls_lo, off);
            ls_hi += __shfl_xor_sync(0xffffffffu, ls_hi, off);
        }
        l_lo = l_lo * corr_lo + ls_lo;
        l_hi = l_hi * corr_hi + ls_hi;

        #pragma unroll
        for (int j = 0; j < 16; ++j) {
            oacc[j][0] *= corr_lo; oacc[j][1] *= corr_lo;
            oacc[j][2] *= corr_hi; oacc[j][3] *= corr_hi;
        }

        // ---- O += P V ----
        #pragma unroll
        for (int s2 = 0; s2 < 4; ++s2) {
            uint32_t a[4] = {ph_lo[2 * s2], ph_hi[2 * s2], ph_lo[2 * s2 + 1], ph_hi[2 * s2 + 1]};
            uint32_t vv[16][2];
            #pragma unroll
            for (int p = 0; p < 8; ++p) {
                int row = p * 16 + lrow;
                int ch  = 2 * s2 + lchq;
                int cp  = ch ^ (row & 7);
                ldsm_x4(vv[2 * p][0], vv[2 * p][1], vv[2 * p + 1][0], vv[2 * p + 1][1],
                        vbuf + row * 128 + cp * 16);
            }
            #pragma unroll
            for (int j = 0; j < 16; ++j)
                mma_f16(oacc[j], a, vv[j]);
        }
    }
#undef PREF

    float inv_lo = 1.0f / l_lo;
    float inv_hi = 1.0f / l_hi;
    __half* o_lo = O + (size_t)(b * S_ + q0 + r_lo) * D_ + h * HD_;
    __half* o_hi = O + (size_t)(b * S_ + q0 + r_hi) * D_ + h * HD_;
    #pragma unroll
    for (int j = 0; j < 16; ++j) {
        int c = j * 8 + 2 * t;
        *(__half2*)(o_lo + c) = __floats2half2_rn(oacc[j][0] * inv_lo, oacc[j][1] * inv_lo);
        *(__half2*)(o_hi + c) = __floats2half2_rn(oacc[j][2] * inv_hi, oacc[j][3] * inv_hi);
    }
}

// =================================================================
extern "C" void kernel_launch(void* const* d_in, const int* in_sizes, int n_in,
                              void* d_out, int out_size) {
    const float* x  = (const float*)d_in[0];
    const float* cs = (const float*)d_in[1];
    const float* sn = (const float*)d_in[2];
    const float* wq = (const float*)d_in[3];
    const float* wk = (const float*)d_in[4];
    const float* wv = (const float*)d_in[5];
    const float* wo = (const float*)d_in[6];
    float* out = (float*)d_out;

    __half *xh, *qh, *kh, *vt, *oh, *wqkvt, *wot;
    cudaGetSymbolAddress((void**)&xh,    g_xh);
    cudaGetSymbolAddress((void**)&qh,    g_qh);
    cudaGetSymbolAddress((void**)&kh,    g_kh);
    cudaGetSymbolAddress((void**)&vt,    g_vt);
    cudaGetSymbolAddress((void**)&oh,    g_oh);
    cudaGetSymbolAddress((void**)&wqkvt, g_wqkvt);
    cudaGetSymbolAddress((void**)&wot,   g_wot);

    cudaFuncSetAttribute(attn_h,    cudaFuncAttributeMaxDynamicSharedMemorySize, ATTN_SMEM);
    cudaFuncSetAttribute(hgemm_qkv, cudaFuncAttributeMaxDynamicSharedMemorySize, HG3_SMEM);
    cudaFuncSetAttribute(hgemm_out, cudaFuncAttributeMaxDynamicSharedMemorySize, HG3_SMEM);

    const int M    = B_ * S_;       // 4096
    const int NQKV = 4096;

    // launches 1-3; capture slot #4 = hgemm_qkv
    int nx4 = (B_ * S_ * D_) / 4;
    f2h_kernel<<<(nx4 + 255) / 256, 256>>>(x, xh, nx4);
    trans_all<<<12288, dim3(32, 8)>>>(wq, wk, wv, wo, wqkvt, wot);
    nop_kernel<<<1, 32>>>();

    hgemm_qkv<<<dim3(NQKV / 128, M / 128), 128, HG3_SMEM>>>(xh, wqkvt, cs, sn, qh, kh, vt);

    attn_h<<<dim3(S_ / 64, H_, B_), 128, ATTN_SMEM>>>(qh, kh, vt, oh);

    hgemm_out<<<dim3(D_ / 128, M / 128), 128, HG3_SMEM>>>(oh, wot, out, D_);
}

// round 14
// speedup vs baseline: 1.0211x; 1.0211x over previous
#include <cuda_runtime.h>
#include <cuda_fp16.h>
#include <cstdint>

#define B_   2
#define S_   2048
#define D_   2048
#define H_   16
#define KVH_ 8
#define HD_  128

// ---------------- scratch (no allocations allowed) ----------------
__device__ __half g_xh   [B_ * S_ * D_];
__device__ __half g_qh   [B_ * S_ * D_];
__device__ __half g_kh   [B_ * S_ * KVH_ * HD_];
__device__ __half g_vt   [(KVH_ * HD_) * (B_ * S_)];   // V^T  [1024][4096]
__device__ __half g_oh   [B_ * S_ * D_];
__device__ __half g_wqkvt[(D_ + 2 * KVH_ * HD_) * D_]; // [4096][2048]: wq^T|wk^T|wv^T
__device__ __half g_wot  [D_ * D_];

// ---------------- helpers ----------------
__device__ __forceinline__ void cpa16(uint32_t dst, const void* src) {
    asm volatile("cp.async.cg.shared.global [%0], [%1], 16;" :: "r"(dst), "l"(src));
}
__device__ __forceinline__ void cpa_commit() { asm volatile("cp.async.commit_group;"); }
__device__ __forceinline__ void cpa_wait0()  { asm volatile("cp.async.wait_group 0;"); }
__device__ __forceinline__ void cpa_wait1()  { asm volatile("cp.async.wait_group 1;"); }
__device__ __forceinline__ void mma_f16(float c[4], const uint32_t a[4], const uint32_t b[2]) {
    asm volatile(
        "mma.sync.aligned.m16n8k16.row.col.f32.f16.f16.f32 "
        "{%0,%1,%2,%3}, {%4,%5,%6,%7}, {%8,%9}, {%0,%1,%2,%3};"
        : "+f"(c[0]), "+f"(c[1]), "+f"(c[2]), "+f"(c[3])
        : "r"(a[0]), "r"(a[1]), "r"(a[2]), "r"(a[3]), "r"(b[0]), "r"(b[1]));
}
__device__ __forceinline__ void ldsm_x4(uint32_t& r0, uint32_t& r1, uint32_t& r2, uint32_t& r3,
                                        uint32_t addr) {
    asm volatile("ldmatrix.sync.aligned.m8n8.x4.shared.b16 {%0,%1,%2,%3}, [%4];"
                 : "=r"(r0), "=r"(r1), "=r"(r2), "=r"(r3) : "r"(addr));
}
__device__ __forceinline__ uint32_t smem_u32(const void* p) {
    return (uint32_t)__cvta_generic_to_shared(p);
}
__device__ __forceinline__ uint32_t h2u(__half2 h) { return *(uint32_t*)&h; }

// =================================================================
// Prepass: one launch does x->half AND all 4 weight transposes.
// blocks [0, 8192): f2h over x (8.39M elements = 2.097M float4)
// blocks [8192, 20480): 32x32 transpose tiles of wq|wk|wv|wo
// =================================================================
__global__ void prep_kernel(const float* __restrict__ x,
                            const float* __restrict__ wq, const float* __restrict__ wk,
                            const float* __restrict__ wv, const float* __restrict__ wo,
                            __half* __restrict__ xh,
                            __half* __restrict__ wqkvt, __half* __restrict__ wot) {
    __shared__ float tb[32][33];
    int id = blockIdx.x;
    int tid = threadIdx.x;
    if (id < 8192) {
        int i = id * 256 + tid;              // n4 = 2,097,152 exactly = 8192*256
        float4 v = ((const float4*)x)[i];
        __half2 a = __floats2half2_rn(v.x, v.y);
        __half2 b = __floats2half2_rn(v.z, v.w);
        ((uint2*)xh)[i] = make_uint2(h2u(a), h2u(b));
        return;
    }
    id -= 8192;
    const float* W;
    __half* WT;
    int N;
    if (id < 4096)      { W = wq; WT = wqkvt;                           N = 2048; }
    else if (id < 6144) { W = wk; WT = wqkvt + 2048 * 2048; id -= 4096; N = 1024; }
    else if (id < 8192) { W = wv; WT = wqkvt + 3072 * 2048; id -= 6144; N = 1024; }
    else                { W = wo; WT = wot;                 id -= 8192; N = 2048; }
    int nb = N / 32;
    int n0 = (id % nb) * 32, k0 = (id / nb) * 32;
    int tx = tid & 31, ty = tid >> 5;
    #pragma unroll
    for (int i = 0; i < 4; ++i)
        tb[ty + i * 8][tx] = W[(size_t)(k0 + ty + i * 8) * N + n0 + tx];
    __syncthreads();
    #pragma unroll
    for (int i = 0; i < 4; ++i)
        WT[(size_t)(n0 + ty + i * 8) * 2048 + k0 + tx] = __float2half_rn(tb[tx][ty + i * 8]);
}

// =================================================================
// GEMM mainloop (R12/R10 proven): 128x128 CTA, 4 warps (2x2 of 64x64),
// BK=64, 2-stage cp.async, ldmatrix preloaded fragments, 2 CTAs/SM.
// smem: A stages @0,16384 ; B stages @32768,49152. 64KB/CTA.
// =================================================================
#define HG3_SMEM 65536

#define GEMM3_MAIN(A_, Bt_, Kdim)                                                       \
    extern __shared__ char smh[];                                                       \
    const uint32_t sbase = smem_u32(smh);                                               \
    const int tid  = threadIdx.x, lane = tid & 31, w = tid >> 5;                        \
    const int g    = lane >> 2, t4 = lane & 3;                                          \
    const int wm   = w >> 1, wn = w & 1;                                                \
    const int bm   = blockIdx.y << 7, bn = blockIdx.x << 7;                             \
    const int sr   = tid >> 3, sc = tid & 7;                                            \
    const __half* aBase = A_ + (size_t)(bm + sr) * (Kdim) + sc * 8;                     \
    const __half* bBase = Bt_ + (size_t)(bn + sr) * (Kdim) + sc * 8;                    \
    const uint32_t sD0 = (uint32_t)(sr * 128 + ((sc ^ (sr & 7)) << 4));                 \
    const int arow0 = wm * 64 + ((lane >> 3) & 1) * 8 + (lane & 7);                     \
    const int achq  = lane >> 4;                                                        \
    const int brow0 = wn * 64 + (lane >> 4) * 8 + (lane & 7);                           \
    const int bchq  = (lane >> 3) & 1;                                                  \
    float acc[4][8][4];                                                                 \
    _Pragma("unroll")                                                                   \
    for (int i = 0; i < 4; ++i)                                                         \
        _Pragma("unroll")                                                               \
        for (int j = 0; j < 8; ++j)                                                     \
            _Pragma("unroll")                                                           \
            for (int r = 0; r < 4; ++r) acc[i][j][r] = 0.f;                             \
    const int ktiles = (Kdim) >> 6;                                                     \
    _Pragma("unroll")                                                                   \
    for (int i = 0; i < 8; ++i) cpa16(sbase + sD0 + i * 2048u, aBase + (size_t)i * 16 * (Kdim)); \
    _Pragma("unroll")                                                                   \
    for (int i = 0; i < 8; ++i) cpa16(sbase + 32768u + sD0 + i * 2048u, bBase + (size_t)i * 16 * (Kdim)); \
    cpa_commit();                                                                       \
    for (int tt = 0; tt < ktiles; ++tt) {                                               \
        if (tt + 1 < ktiles) {                                                          \
            uint32_t ao = ((tt + 1) & 1) * 16384u;                                      \
            uint32_t bo = 32768u + ((tt + 1) & 1) * 16384u;                             \
            const __half* ap = aBase + (size_t)(tt + 1) * 64;                           \
            const __half* bp = bBase + (size_t)(tt + 1) * 64;                           \
            _Pragma("unroll")                                                           \
            for (int i = 0; i < 8; ++i) cpa16(sbase + ao + sD0 + i * 2048u, ap + (size_t)i * 16 * (Kdim)); \
            _Pragma("unroll")                                                           \
            for (int i = 0; i < 8; ++i) cpa16(sbase + bo + sD0 + i * 2048u, bp + (size_t)i * 16 * (Kdim)); \
            cpa_commit();                                                               \
            cpa_wait1();                                                                \
        } else {                                                                        \
            cpa_wait0();                                                                \
        }                                                                               \
        __syncthreads();                                                                \
        const uint32_t sA = sbase + (tt & 1) * 16384u;                                  \
        const uint32_t sB = sbase + 32768u + (tt & 1) * 16384u;                         \
        _Pragma("unroll")                                                               \
        for (int s = 0; s < 4; ++s) {                                                   \
            uint32_t a[4][4], b[8][2];                                                  \
            _Pragma("unroll")                                                           \
            for (int i = 0; i < 4; ++i) {                                               \
                int row = arow0 + i * 16;                                               \
                int ch  = (2 * s + achq) ^ (row & 7);                                   \
                ldsm_x4(a[i][0], a[i][1], a[i][2], a[i][3], sA + row * 128 + (ch << 4)); \
            }                                                                           \
            _Pragma("unroll")                                                           \
            for (int p = 0; p < 4; ++p) {                                               \
                int row = brow0 + p * 16;                                               \
                int ch  = (2 * s + bchq) ^ (row & 7);                                   \
                ldsm_x4(b[2 * p][0], b[2 * p][1], b[2 * p + 1][0], b[2 * p + 1][1],     \
                        sB + row * 128 + (ch << 4));                                    \
            }                                                                           \
            _Pragma("unroll")                                                           \
            for (int i = 0; i < 4; ++i)                                                 \
                _Pragma("unroll")                                                       \
                for (int j = 0; j < 8; ++j)                                             \
                    mma_f16(acc[i][j], a[i], b[j]);                                     \
        }                                                                               \
        __syncthreads();                                                                \
    }

// =================================================================
// Fused QKV projection + RoPE epilogue.
// Q scale folds in log2(e): attention softmax runs in exp2 domain.
// =================================================================
__global__ __launch_bounds__(128, 2)
void hgemm_qkv(const __half* __restrict__ A, const __half* __restrict__ Bt,
               const float* __restrict__ cs, const float* __restrict__ sn,
               __half* __restrict__ Qo, __half* __restrict__ Ko, __half* __restrict__ Vt) {
    GEMM3_MAIN(A, Bt, D_)

    const float SCALE2 = 0.12751974007636297f;  // (1/sqrt(128)) * log2(e)
    const int cc = t4 * 2;
    if (bn < D_) {
        #pragma unroll
        for (int i = 0; i < 4; ++i)
            #pragma unroll
            for (int j = 0; j < 8; ++j) {
                int row = bm + wm * 64 + i * 16 + g;
                int col = bn + wn * 64 + j * 8 + cc;
                int dd  = (col & 127) >> 1;
                int s_lo = row & (S_ - 1), s_hi = (row + 8) & (S_ - 1);
                float c0 = cs[s_lo * 64 + dd], si0 = sn[s_lo * 64 + dd];
                float c1 = cs[s_hi * 64 + dd], si1 = sn[s_hi * 64 + dd];
                float r0 = (acc[i][j][0] * c0 - acc[i][j][1] * si0) * SCALE2;
                float r1 = (acc[i][j][0] * si0 + acc[i][j][1] * c0) * SCALE2;
                float r2 = (acc[i][j][2] * c1 - acc[i][j][3] * si1) * SCALE2;
                float r3 = (acc[i][j][2] * si1 + acc[i][j][3] * c1) * SCALE2;
                *(__half2*)(Qo + (size_t)row * D_ + col)       = __floats2half2_rn(r0, r1);
                *(__half2*)(Qo + (size_t)(row + 8) * D_ + col) = __floats2half2_rn(r2, r3);
            }
    } else if (bn < D_ + KVH_ * HD_) {
        #pragma unroll
        for (int i = 0; i < 4; ++i)
            #pragma unroll
            for (int j = 0; j < 8; ++j) {
                int row = bm + wm * 64 + i * 16 + g;
                int col = bn - D_ + wn * 64 + j * 8 + cc;
                int dd  = (col & 127) >> 1;
                int s_lo = row & (S_ - 1), s_hi = (row + 8) & (S_ - 1);
                float c0 = cs[s_lo * 64 + dd], si0 = sn[s_lo * 64 + dd];
                float c1 = cs[s_hi * 64 + dd], si1 = sn[s_hi * 64 + dd];
                float r0 = acc[i][j][0] * c0 - acc[i][j][1] * si0;
                float r1 = acc[i][j][0] * si0 + acc[i][j][1] * c0;
                float r2 = acc[i][j][2] * c1 - acc[i][j][3] * si1;
                float r3 = acc[i][j][2] * si1 + acc[i][j][3] * c1;
                *(__half2*)(Ko + (size_t)row * (KVH_ * HD_) + col)       = __floats2half2_rn(r0, r1);
                *(__half2*)(Ko + (size_t)(row + 8) * (KVH_ * HD_) + col) = __floats2half2_rn(r2, r3);
            }
    } else {
        const int M = B_ * S_;
        #pragma unroll
        for (int i = 0; i < 4; ++i)
            #pragma unroll
            for (int j = 0; j < 8; ++j) {
                int row = bm + wm * 64 + i * 16 + g;
                int col = bn - (D_ + KVH_ * HD_) + wn * 64 + j * 8 + cc;
                Vt[(size_t)col * M + row]           = __float2half_rn(acc[i][j][0]);
                Vt[(size_t)(col + 1) * M + row]     = __float2half_rn(acc[i][j][1]);
                Vt[(size_t)col * M + row + 8]       = __float2half_rn(acc[i][j][2]);
                Vt[(size_t)(col + 1) * M + row + 8] = __float2half_rn(acc[i][j][3]);
            }
    }
}

// =================================================================
// O-projection GEMM: half in, fp32 out.
// =================================================================
__global__ __launch_bounds__(128, 2)
void hgemm_out(const __half* __restrict__ A, const __half* __restrict__ Bt,
               float* __restrict__ Cf, int N) {
    GEMM3_MAIN(A, Bt, D_)
    const int cc = t4 * 2;
    #pragma unroll
    for (int i = 0; i < 4; ++i)
        #pragma unroll
        for (int j = 0; j < 8; ++j) {
            int row = bm + wm * 64 + i * 16 + g;
            int col = bn + wn * 64 + j * 8 + cc;
            *(float2*)(Cf + (size_t)row * N + col)       = make_float2(acc[i][j][0], acc[i][j][1]);
            *(float2*)(Cf + (size_t)(row + 8) * N + col) = make_float2(acc[i][j][2], acc[i][j][3]);
        }
}

// =================================================================
// FP16 flash attention (R12 proven): 64 Q-rows per CTA, 128 threads,
// 2-stage cp.async, ldmatrix, 2 CTAs/SM. Softmax in exp2 domain
// (Q pre-scaled by log2(e)/sqrt(HD)).
// smem: 2 stages x (K 16KB + V 16KB) = 64KB.
// =================================================================
#define ATTN_SMEM 65536

__global__ __launch_bounds__(128, 2)
void attn_h(const __half* __restrict__ Q, const __half* __restrict__ Kg,
            const __half* __restrict__ Vt, __half* __restrict__ O) {
    extern __shared__ char smc[];
    const uint32_t sbase = smem_u32(smc);
    const int tid = threadIdx.x, lane = tid & 31, w = tid >> 5;
    const int g = lane >> 2, t = lane & 3;

    const int qtile = gridDim.x - 1 - blockIdx.x;   // heavy CTAs first
    const int h = blockIdx.y, b = blockIdx.z;
    const int q0 = qtile * 64, kh = h >> 1;
    const int r_lo = w * 16 + g, r_hi = r_lo + 8;

    const int lrow = ((lane >> 4) << 3) + (lane & 7);
    const int lchq = (lane >> 3) & 1;

    const __half* qlo = Q + (size_t)(b * S_ + q0 + r_lo) * D_ + h * HD_;
    const __half* qhi = Q + (size_t)(b * S_ + q0 + r_hi) * D_ + h * HD_;
    uint32_t qa[8][4];
    #pragma unroll
    for (int s = 0; s < 8; ++s) {
        qa[s][0] = *(const uint32_t*)(qlo + s * 16 + 2 * t);
        qa[s][1] = *(const uint32_t*)(qhi + s * 16 + 2 * t);
        qa[s][2] = *(const uint32_t*)(qlo + s * 16 + 2 * t + 8);
        qa[s][3] = *(const uint32_t*)(qhi + s * 16 + 2 * t + 8);
    }

    const __half* kbp = Kg + (size_t)b * S_ * (KVH_ * HD_) + kh * HD_;
    const __half* vtp = Vt + (size_t)(kh * HD_) * (B_ * S_) + b * S_;

    float m_lo = -1e30f, m_hi = -1e30f, l_lo = 0.f, l_hi = 0.f;
    float oacc[16][4];
    #pragma unroll
    for (int j = 0; j < 16; ++j)
        #pragma unroll
        for (int r = 0; r < 4; ++r) oacc[j][r] = 0.f;

    const int nkt = qtile + 1;

    // K: 64 rows x 16 chunks (256B rows); V: 128 rows x 8 chunks (128B rows)
#define PREF(ktp) do {                                                             \
        int k0p = (ktp) * 64;                                                      \
        uint32_t kb2 = sbase + ((ktp) & 1) * 32768u;                               \
        uint32_t vb2 = kb2 + 16384u;                                               \
        _Pragma("unroll")                                                          \
        for (int i = 0; i < 8; ++i) {                                              \
            int idx = tid + i * 128; int r = idx >> 4, c = idx & 15;               \
            int cp = (c & 8) | ((c ^ (r & 7)) & 7);                                \
            cpa16(kb2 + (uint32_t)(r * 256 + cp * 16),                             \
                  kbp + (size_t)(k0p + r) * (KVH_ * HD_) + c * 8);                 \
        }                                                                          \
        _Pragma("unroll")                                                          \
        for (int i = 0; i < 8; ++i) {                                              \
            int idx = tid + i * 128; int d = idx >> 3, c = idx & 7;                \
            int cp = c ^ (d & 7);                                                  \
            cpa16(vb2 + (uint32_t)(d * 128 + cp * 16),                             \
                  vtp + (size_t)d * (B_ * S_) + k0p + c * 8);                      \
        }                                                                          \
        cpa_commit();                                                              \
    } while (0)

    PREF(0);

    for (int kt = 0; kt < nkt; ++kt) {
        const int k0 = kt * 64;
        if (kt + 1 < nkt) { PREF(kt + 1); cpa_wait1(); }
        else              { cpa_wait0(); }
        __syncthreads();

        const uint32_t kbuf = sbase + (kt & 1) * 32768u;
        const uint32_t vbuf = kbuf + 16384u;

        // ---- S = Q K^T (already in log2 domain) ----
        float sacc[8][4];
        #pragma unroll
        for (int j = 0; j < 8; ++j)
            #pragma unroll
            for (int r = 0; r < 4; ++r) sacc[j][r] = 0.f;

        #pragma unroll
        for (int s = 0; s < 8; ++s) {
            uint32_t bb[8][2];
            #pragma unroll
            for (int p = 0; p < 4; ++p) {
                int row = p * 16 + lrow;
                int ch  = 2 * s + lchq;
                int cp  = (ch & 8) | ((ch ^ (row & 7)) & 7);
                ldsm_x4(bb[2 * p][0], bb[2 * p][1], bb[2 * p + 1][0], bb[2 * p + 1][1],
                        kbuf + row * 256 + cp * 16);
            }
            #pragma unroll
            for (int j = 0; j < 8; ++j)
                mma_f16(sacc[j], qa[s], bb[j]);
        }

        // ---- causal mask (diagonal tile only) ----
        if (kt == qtile) {
            const int lim_lo = q0 + r_lo - k0;
            const int lim_hi = q0 + r_hi - k0;
            #pragma unroll
            for (int j = 0; j < 8; ++j) {
                int c0 = j * 8 + 2 * t, c1 = c0 + 1;
                if (c0 > lim_lo) sacc[j][0] = -1e30f;
                if (c1 > lim_lo) sacc[j][1] = -1e30f;
                if (c0 > lim_hi) sacc[j][2] = -1e30f;
                if (c1 > lim_hi) sacc[j][3] = -1e30f;
            }
        }

        // ---- online softmax (exp2 domain) ----
        float mv_lo = -1e30f, mv_hi = -1e30f;
        #pragma unroll
        for (int j = 0; j < 8; ++j) {
            mv_lo = fmaxf(mv_lo, fmaxf(sacc[j][0], sacc[j][1]));
            mv_hi = fmaxf(mv_hi, fmaxf(sacc[j][2], sacc[j][3]));
        }
        #pragma unroll
        for (int off = 1; off <= 2; off <<= 1) {
            mv_lo = fmaxf(mv_lo, __shfl_xor_sync(0xffffffffu, mv_lo, off));
            mv_hi = fmaxf(mv_hi, __shfl_xor_sync(0xffffffffu, mv_hi, off));
        }
        float mn_lo = fmaxf(m_lo, mv_lo);
        float mn_hi = fmaxf(m_hi, mv_hi);
        float corr_lo = exp2f(m_lo - mn_lo);
        float corr_hi = exp2f(m_hi - mn_hi);
        m_lo = mn_lo; m_hi = mn_hi;

        float ls_lo = 0.f, ls_hi = 0.f;
        uint32_t ph_lo[8], ph_hi[8];
        #pragma unroll
        for (int j = 0; j < 8; ++j) {
            float p0 = exp2f(sacc[j][0] - mn_lo);
            float p1 = exp2f(sacc[j][1] - mn_lo);
            float p2 = exp2f(sacc[j][2] - mn_hi);
            float p3 = exp2f(sacc[j][3] - mn_hi);
            ls_lo += p0 + p1;
            ls_hi += p2 + p3;
            ph_lo[j] = h2u(__floats2half2_rn(p0, p1));
            ph_hi[j] = h2u(__floats2half2_rn(p2, p3));
        }
        #pragma unroll
        for (int off = 1; off <= 2; off <<= 1) {
            ls_lo += __shfl_xor_sync(0xffffffffu, ls_lo, off);
            ls_hi += __shfl_xor_sync(0xffffffffu, ls_hi, off);
        }
        l_lo = l_lo * corr_lo + ls_lo;
        l_hi = l_hi * corr_hi + ls_hi;

        #pragma unroll
        for (int j = 0; j < 16; ++j) {
            oacc[j][0] *= corr_lo; oacc[j][1] *= corr_lo;
            oacc[j][2] *= corr_hi; oacc[j][3] *= corr_hi;
        }

        // ---- O += P V ----
        #pragma unroll
        for (int s2 = 0; s2 < 4; ++s2) {
            uint32_t a[4] = {ph_lo[2 * s2], ph_hi[2 * s2], ph_lo[2 * s2 + 1], ph_hi[2 * s2 + 1]};
            uint32_t vv[16][2];
            #pragma unroll
            for (int p = 0; p < 8; ++p) {
                int row = p * 16 + lrow;
                int ch  = 2 * s2 + lchq;
                int cp  = ch ^ (row & 7);
                ldsm_x4(vv[2 * p][0], vv[2 * p][1], vv[2 * p + 1][0], vv[2 * p + 1][1],
                        vbuf + row * 128 + cp * 16);
            }
            #pragma unroll
            for (int j = 0; j < 16; ++j)
                mma_f16(oacc[j], a, vv[j]);
        }
        __syncthreads();
    }
#undef PREF

    float inv_lo = 1.0f / l_lo;
    float inv_hi = 1.0f / l_hi;
    __half* o_lo = O + (size_t)(b * S_ + q0 + r_lo) * D_ + h * HD_;
    __half* o_hi = O + (size_t)(b * S_ + q0 + r_hi) * D_ + h * HD_;
    #pragma unroll
    for (int j = 0; j < 16; ++j) {
        int c = j * 8 + 2 * t;
        *(__half2*)(o_lo + c) = __floats2half2_rn(oacc[j][0] * inv_lo, oacc[j][1] * inv_lo);
        *(__half2*)(o_hi + c) = __floats2half2_rn(oacc[j][2] * inv_hi, oacc[j][3] * inv_hi);
    }
}

// =================================================================
extern "C" void kernel_launch(void* const* d_in, const int* in_sizes, int n_in,
                              void* d_out, int out_size) {
    const float* x  = (const float*)d_in[0];
    const float* cs = (const float*)d_in[1];
    const float* sn = (const float*)d_in[2];
    const float* wq = (const float*)d_in[3];
    const float* wk = (const float*)d_in[4];
    const float* wv = (const float*)d_in[5];
    const float* wo = (const float*)d_in[6];
    float* out = (float*)d_out;

    __half *xh, *qh, *kh, *vt, *oh, *wqkvt, *wot;
    cudaGetSymbolAddress((void**)&xh,    g_xh);
    cudaGetSymbolAddress((void**)&qh,    g_qh);
    cudaGetSymbolAddress((void**)&kh,    g_kh);
    cudaGetSymbolAddress((void**)&vt,    g_vt);
    cudaGetSymbolAddress((void**)&oh,    g_oh);
    cudaGetSymbolAddress((void**)&wqkvt, g_wqkvt);
    cudaGetSymbolAddress((void**)&wot,   g_wot);

    cudaFuncSetAttribute(attn_h,    cudaFuncAttributeMaxDynamicSharedMemorySize, ATTN_SMEM);
    cudaFuncSetAttribute(hgemm_qkv, cudaFuncAttributeMaxDynamicSharedMemorySize, HG3_SMEM);
    cudaFuncSetAttribute(hgemm_out, cudaFuncAttributeMaxDynamicSharedMemorySize, HG3_SMEM);

    const int M    = B_ * S_;       // 4096
    const int NQKV = 4096;

    prep_kernel<<<20480, 256>>>(x, wq, wk, wv, wo, xh, wqkvt, wot);

    hgemm_qkv<<<dim3(NQKV / 128, M / 128), 128, HG3_SMEM>>>(xh, wqkvt, cs, sn, qh, kh, vt);

    attn_h<<<dim3(S_ / 64, H_, B_), 128, ATTN_SMEM>>>(qh, kh, vt, oh);

    hgemm_out<<<dim3(D_ / 128, M / 128), 128, HG3_SMEM>>>(oh, wot, out, D_);
}

// round 15
// speedup vs baseline: 1.0258x; 1.0046x over previous
#include <cuda_runtime.h>
#include <cuda_fp16.h>
#include <cstdint>

#define B_   2
#define S_   2048
#define D_   2048
#define H_   16
#define KVH_ 8
#define HD_  128

// ---------------- scratch (no allocations allowed) ----------------
__device__ __half g_xh   [B_ * S_ * D_];
__device__ __half g_qh   [B_ * S_ * D_];
__device__ __half g_kh   [B_ * S_ * KVH_ * HD_];
__device__ __half g_vt   [(KVH_ * HD_) * (B_ * S_)];   // V^T  [1024][4096]
__device__ __half g_oh   [B_ * S_ * D_];
__device__ __half g_wqkvt[(D_ + 2 * KVH_ * HD_) * D_]; // [4096][2048]: wq^T|wk^T|wv^T
__device__ __half g_wot  [D_ * D_];

// ---------------- helpers ----------------
__device__ __forceinline__ void cpa16(uint32_t dst, const void* src) {
    asm volatile("cp.async.cg.shared.global [%0], [%1], 16;" :: "r"(dst), "l"(src));
}
__device__ __forceinline__ void cpa_commit() { asm volatile("cp.async.commit_group;"); }
__device__ __forceinline__ void cpa_wait0()  { asm volatile("cp.async.wait_group 0;"); }
__device__ __forceinline__ void cpa_wait1()  { asm volatile("cp.async.wait_group 1;"); }
__device__ __forceinline__ void mma_f16(float c[4], const uint32_t a[4], const uint32_t b[2]) {
    asm volatile(
        "mma.sync.aligned.m16n8k16.row.col.f32.f16.f16.f32 "
        "{%0,%1,%2,%3}, {%4,%5,%6,%7}, {%8,%9}, {%0,%1,%2,%3};"
        : "+f"(c[0]), "+f"(c[1]), "+f"(c[2]), "+f"(c[3])
        : "r"(a[0]), "r"(a[1]), "r"(a[2]), "r"(a[3]), "r"(b[0]), "r"(b[1]));
}
__device__ __forceinline__ void ldsm_x4(uint32_t& r0, uint32_t& r1, uint32_t& r2, uint32_t& r3,
                                        uint32_t addr) {
    asm volatile("ldmatrix.sync.aligned.m8n8.x4.shared.b16 {%0,%1,%2,%3}, [%4];"
                 : "=r"(r0), "=r"(r1), "=r"(r2), "=r"(r3) : "r"(addr));
}
__device__ __forceinline__ uint32_t smem_u32(const void* p) {
    return (uint32_t)__cvta_generic_to_shared(p);
}
__device__ __forceinline__ uint32_t h2u(__half2 h) { return *(uint32_t*)&h; }
__device__ __forceinline__ uint32_t ex2_h2(uint32_t x) {
    uint32_t r;
    asm("ex2.approx.f16x2 %0, %1;" : "=r"(r) : "r"(x));
    return r;
}

// =================================================================
// Prepass: one launch does x->half AND all 4 weight transposes.
// =================================================================
__global__ void prep_kernel(const float* __restrict__ x,
                            const float* __restrict__ wq, const float* __restrict__ wk,
                            const float* __restrict__ wv, const float* __restrict__ wo,
                            __half* __restrict__ xh,
                            __half* __restrict__ wqkvt, __half* __restrict__ wot) {
    __shared__ float tb[32][33];
    int id = blockIdx.x;
    int tid = threadIdx.x;
    if (id < 8192) {
        int i = id * 256 + tid;
        float4 v = ((const float4*)x)[i];
        __half2 a = __floats2half2_rn(v.x, v.y);
        __half2 b = __floats2half2_rn(v.z, v.w);
        ((uint2*)xh)[i] = make_uint2(h2u(a), h2u(b));
        return;
    }
    id -= 8192;
    const float* W;
    __half* WT;
    int N;
    if (id < 4096)      { W = wq; WT = wqkvt;                           N = 2048; }
    else if (id < 6144) { W = wk; WT = wqkvt + 2048 * 2048; id -= 4096; N = 1024; }
    else if (id < 8192) { W = wv; WT = wqkvt + 3072 * 2048; id -= 6144; N = 1024; }
    else                { W = wo; WT = wot;                 id -= 8192; N = 2048; }
    int nb = N / 32;
    int n0 = (id % nb) * 32, k0 = (id / nb) * 32;
    int tx = tid & 31, ty = tid >> 5;
    #pragma unroll
    for (int i = 0; i < 4; ++i)
        tb[ty + i * 8][tx] = W[(size_t)(k0 + ty + i * 8) * N + n0 + tx];
    __syncthreads();
    #pragma unroll
    for (int i = 0; i < 4; ++i)
        WT[(size_t)(n0 + ty + i * 8) * 2048 + k0 + tx] = __float2half_rn(tb[tx][ty + i * 8]);
}

// =================================================================
// GEMM mainloop (proven): 128x128 CTA, 4 warps (2x2 of 64x64),
// BK=64, 2-stage cp.async, ldmatrix, 2 CTAs/SM. 64KB/CTA.
// =================================================================
#define HG3_SMEM 65536

#define GEMM3_MAIN(A_, Bt_, Kdim)                                                       \
    extern __shared__ char smh[];                                                       \
    const uint32_t sbase = smem_u32(smh);                                               \
    const int tid  = threadIdx.x, lane = tid & 31, w = tid >> 5;                        \
    const int g    = lane >> 2, t4 = lane & 3;                                          \
    const int wm   = w >> 1, wn = w & 1;                                                \
    const int bm   = blockIdx.y << 7, bn = blockIdx.x << 7;                             \
    const int sr   = tid >> 3, sc = tid & 7;                                            \
    const __half* aBase = A_ + (size_t)(bm + sr) * (Kdim) + sc * 8;                     \
    const __half* bBase = Bt_ + (size_t)(bn + sr) * (Kdim) + sc * 8;                    \
    const uint32_t sD0 = (uint32_t)(sr * 128 + ((sc ^ (sr & 7)) << 4));                 \
    const int arow0 = wm * 64 + ((lane >> 3) & 1) * 8 + (lane & 7);                     \
    const int achq  = lane >> 4;                                                        \
    const int brow0 = wn * 64 + (lane >> 4) * 8 + (lane & 7);                           \
    const int bchq  = (lane >> 3) & 1;                                                  \
    float acc[4][8][4];                                                                 \
    _Pragma("unroll")                                                                   \
    for (int i = 0; i < 4; ++i)                                                         \
        _Pragma("unroll")                                                               \
        for (int j = 0; j < 8; ++j)                                                     \
            _Pragma("unroll")                                                           \
            for (int r = 0; r < 4; ++r) acc[i][j][r] = 0.f;                             \
    const int ktiles = (Kdim) >> 6;                                                     \
    _Pragma("unroll")                                                                   \
    for (int i = 0; i < 8; ++i) cpa16(sbase + sD0 + i * 2048u, aBase + (size_t)i * 16 * (Kdim)); \
    _Pragma("unroll")                                                                   \
    for (int i = 0; i < 8; ++i) cpa16(sbase + 32768u + sD0 + i * 2048u, bBase + (size_t)i * 16 * (Kdim)); \
    cpa_commit();                                                                       \
    for (int tt = 0; tt < ktiles; ++tt) {                                               \
        if (tt + 1 < ktiles) {                                                          \
            uint32_t ao = ((tt + 1) & 1) * 16384u;                                      \
            uint32_t bo = 32768u + ((tt + 1) & 1) * 16384u;                             \
            const __half* ap = aBase + (size_t)(tt + 1) * 64;                           \
            const __half* bp = bBase + (size_t)(tt + 1) * 64;                           \
            _Pragma("unroll")                                                           \
            for (int i = 0; i < 8; ++i) cpa16(sbase + ao + sD0 + i * 2048u, ap + (size_t)i * 16 * (Kdim)); \
            _Pragma("unroll")                                                           \
            for (int i = 0; i < 8; ++i) cpa16(sbase + bo + sD0 + i * 2048u, bp + (size_t)i * 16 * (Kdim)); \
            cpa_commit();                                                               \
            cpa_wait1();                                                                \
        } else {                                                                        \
            cpa_wait0();                                                                \
        }                                                                               \
        __syncthreads();                                                                \
        const uint32_t sA = sbase + (tt & 1) * 16384u;                                  \
        const uint32_t sB = sbase + 32768u + (tt & 1) * 16384u;                         \
        _Pragma("unroll")                                                               \
        for (int s = 0; s < 4; ++s) {                                                   \
            uint32_t a[4][4], b[8][2];                                                  \
            _Pragma("unroll")                                                           \
            for (int i = 0; i < 4; ++i) {                                               \
                int row = arow0 + i * 16;                                               \
                int ch  = (2 * s + achq) ^ (row & 7);                                   \
                ldsm_x4(a[i][0], a[i][1], a[i][2], a[i][3], sA + row * 128 + (ch << 4)); \
            }                                                                           \
            _Pragma("unroll")                                                           \
            for (int p = 0; p < 4; ++p) {                                               \
                int row = brow0 + p * 16;                                               \
                int ch  = (2 * s + bchq) ^ (row & 7);                                   \
                ldsm_x4(b[2 * p][0], b[2 * p][1], b[2 * p + 1][0], b[2 * p + 1][1],     \
                        sB + row * 128 + (ch << 4));                                    \
            }                                                                           \
            _Pragma("unroll")                                                           \
            for (int i = 0; i < 4; ++i)                                                 \
                _Pragma("unroll")                                                       \
                for (int j = 0; j < 8; ++j)                                             \
                    mma_f16(acc[i][j], a[i], b[j]);                                     \
        }                                                                               \
        __syncthreads();                                                                \
    }

// =================================================================
// Fused QKV projection + RoPE epilogue (Q scaled by log2e/sqrt(HD)).
// =================================================================
__global__ __launch_bounds__(128, 2)
void hgemm_qkv(const __half* __restrict__ A, const __half* __restrict__ Bt,
               const float* __restrict__ cs, const float* __restrict__ sn,
               __half* __restrict__ Qo, __half* __restrict__ Ko, __half* __restrict__ Vt) {
    GEMM3_MAIN(A, Bt, D_)

    const float SCALE2 = 0.12751974007636297f;  // (1/sqrt(128)) * log2(e)
    const int cc = t4 * 2;
    if (bn < D_) {
        #pragma unroll
        for (int i = 0; i < 4; ++i)
            #pragma unroll
            for (int j = 0; j < 8; ++j) {
                int row = bm + wm * 64 + i * 16 + g;
                int col = bn + wn * 64 + j * 8 + cc;
                int dd  = (col & 127) >> 1;
                int s_lo = row & (S_ - 1), s_hi = (row + 8) & (S_ - 1);
                float c0 = cs[s_lo * 64 + dd], si0 = sn[s_lo * 64 + dd];
                float c1 = cs[s_hi * 64 + dd], si1 = sn[s_hi * 64 + dd];
                float r0 = (acc[i][j][0] * c0 - acc[i][j][1] * si0) * SCALE2;
                float r1 = (acc[i][j][0] * si0 + acc[i][j][1] * c0) * SCALE2;
                float r2 = (acc[i][j][2] * c1 - acc[i][j][3] * si1) * SCALE2;
                float r3 = (acc[i][j][2] * si1 + acc[i][j][3] * c1) * SCALE2;
                *(__half2*)(Qo + (size_t)row * D_ + col)       = __floats2half2_rn(r0, r1);
                *(__half2*)(Qo + (size_t)(row + 8) * D_ + col) = __floats2half2_rn(r2, r3);
            }
    } else if (bn < D_ + KVH_ * HD_) {
        #pragma unroll
        for (int i = 0; i < 4; ++i)
            #pragma unroll
            for (int j = 0; j < 8; ++j) {
                int row = bm + wm * 64 + i * 16 + g;
                int col = bn - D_ + wn * 64 + j * 8 + cc;
                int dd  = (col & 127) >> 1;
                int s_lo = row & (S_ - 1), s_hi = (row + 8) & (S_ - 1);
                float c0 = cs[s_lo * 64 + dd], si0 = sn[s_lo * 64 + dd];
                float c1 = cs[s_hi * 64 + dd], si1 = sn[s_hi * 64 + dd];
                float r0 = acc[i][j][0] * c0 - acc[i][j][1] * si0;
                float r1 = acc[i][j][0] * si0 + acc[i][j][1] * c0;
                float r2 = acc[i][j][2] * c1 - acc[i][j][3] * si1;
                float r3 = acc[i][j][2] * si1 + acc[i][j][3] * c1;
                *(__half2*)(Ko + (size_t)row * (KVH_ * HD_) + col)       = __floats2half2_rn(r0, r1);
                *(__half2*)(Ko + (size_t)(row + 8) * (KVH_ * HD_) + col) = __floats2half2_rn(r2, r3);
            }
    } else {
        const int M = B_ * S_;
        #pragma unroll
        for (int i = 0; i < 4; ++i)
            #pragma unroll
            for (int j = 0; j < 8; ++j) {
                int row = bm + wm * 64 + i * 16 + g;
                int col = bn - (D_ + KVH_ * HD_) + wn * 64 + j * 8 + cc;
                Vt[(size_t)col * M + row]           = __float2half_rn(acc[i][j][0]);
                Vt[(size_t)(col + 1) * M + row]     = __float2half_rn(acc[i][j][1]);
                Vt[(size_t)col * M + row + 8]       = __float2half_rn(acc[i][j][2]);
                Vt[(size_t)(col + 1) * M + row + 8] = __float2half_rn(acc[i][j][3]);
            }
    }
}

// =================================================================
// O-projection GEMM: half in, fp32 out.
// =================================================================
__global__ __launch_bounds__(128, 2)
void hgemm_out(const __half* __restrict__ A, const __half* __restrict__ Bt,
               float* __restrict__ Cf, int N) {
    GEMM3_MAIN(A, Bt, D_)
    const int cc = t4 * 2;
    #pragma unroll
    for (int i = 0; i < 4; ++i)
        #pragma unroll
        for (int j = 0; j < 8; ++j) {
            int row = bm + wm * 64 + i * 16 + g;
            int col = bn + wn * 64 + j * 8 + cc;
            *(float2*)(Cf + (size_t)row * N + col)       = make_float2(acc[i][j][0], acc[i][j][1]);
            *(float2*)(Cf + (size_t)(row + 8) * N + col) = make_float2(acc[i][j][2], acc[i][j][3]);
        }
}

// =================================================================
// FP16 flash attention: 64 Q-rows/CTA, 128 threads, 2-stage cp.async,
// ldmatrix, 2 CTAs/SM. Softmax in exp2 domain with ex2.approx.f16x2
// (half the MUFU ops; fp32 max-subtract preserves accuracy).
// =================================================================
#define ATTN_SMEM 65536

__global__ __launch_bounds__(128, 2)
void attn_h(const __half* __restrict__ Q, const __half* __restrict__ Kg,
            const __half* __restrict__ Vt, __half* __restrict__ O) {
    extern __shared__ char smc[];
    const uint32_t sbase = smem_u32(smc);
    const int tid = threadIdx.x, lane = tid & 31, w = tid >> 5;
    const int g = lane >> 2, t = lane & 3;

    const int qtile = gridDim.x - 1 - blockIdx.x;   // heavy CTAs first
    const int h = blockIdx.y, b = blockIdx.z;
    const int q0 = qtile * 64, kh = h >> 1;
    const int r_lo = w * 16 + g, r_hi = r_lo + 8;

    const int lrow = ((lane >> 4) << 3) + (lane & 7);
    const int lchq = (lane >> 3) & 1;

    const __half* qlo = Q + (size_t)(b * S_ + q0 + r_lo) * D_ + h * HD_;
    const __half* qhi = Q + (size_t)(b * S_ + q0 + r_hi) * D_ + h * HD_;
    uint32_t qa[8][4];
    #pragma unroll
    for (int s = 0; s < 8; ++s) {
        qa[s][0] = *(const uint32_t*)(qlo + s * 16 + 2 * t);
        qa[s][1] = *(const uint32_t*)(qhi + s * 16 + 2 * t);
        qa[s][2] = *(const uint32_t*)(qlo + s * 16 + 2 * t + 8);
        qa[s][3] = *(const uint32_t*)(qhi + s * 16 + 2 * t + 8);
    }

    const __half* kbp = Kg + (size_t)b * S_ * (KVH_ * HD_) + kh * HD_;
    const __half* vtp = Vt + (size_t)(kh * HD_) * (B_ * S_) + b * S_;

    float m_lo = -1e30f, m_hi = -1e30f, l_lo = 0.f, l_hi = 0.f;
    float oacc[16][4];
    #pragma unroll
    for (int j = 0; j < 16; ++j)
        #pragma unroll
        for (int r = 0; r < 4; ++r) oacc[j][r] = 0.f;

    const int nkt = qtile + 1;

#define PREF(ktp) do {                                                             \
        int k0p = (ktp) * 64;                                                      \
        uint32_t kb2 = sbase + ((ktp) & 1) * 32768u;                               \
        uint32_t vb2 = kb2 + 16384u;                                               \
        _Pragma("unroll")                                                          \
        for (int i = 0; i < 8; ++i) {                                              \
            int idx = tid + i * 128; int r = idx >> 4, c = idx & 15;               \
            int cp = (c & 8) | ((c ^ (r & 7)) & 7);                                \
            cpa16(kb2 + (uint32_t)(r * 256 + cp * 16),                             \
                  kbp + (size_t)(k0p + r) * (KVH_ * HD_) + c * 8);                 \
        }                                                                          \
        _Pragma("unroll")                                                          \
        for (int i = 0; i < 8; ++i) {                                              \
            int idx = tid + i * 128; int d = idx >> 3, c = idx & 7;                \
            int cp = c ^ (d & 7);                                                  \
            cpa16(vb2 + (uint32_t)(d * 128 + cp * 16),                             \
                  vtp + (size_t)d * (B_ * S_) + k0p + c * 8);                      \
        }                                                                          \
        cpa_commit();                                                              \
    } while (0)

    PREF(0);

    for (int kt = 0; kt < nkt; ++kt) {
        const int k0 = kt * 64;
        if (kt + 1 < nkt) { PREF(kt + 1); cpa_wait1(); }
        else              { cpa_wait0(); }
        __syncthreads();

        const uint32_t kbuf = sbase + (kt & 1) * 32768u;
        const uint32_t vbuf = kbuf + 16384u;

        // ---- S = Q K^T (log2 domain) ----
        float sacc[8][4];
        #pragma unroll
        for (int j = 0; j < 8; ++j)
            #pragma unroll
            for (int r = 0; r < 4; ++r) sacc[j][r] = 0.f;

        #pragma unroll
        for (int s = 0; s < 8; ++s) {
            uint32_t bb[8][2];
            #pragma unroll
            for (int p = 0; p < 4; ++p) {
                int row = p * 16 + lrow;
                int ch  = 2 * s + lchq;
                int cp  = (ch & 8) | ((ch ^ (row & 7)) & 7);
                ldsm_x4(bb[2 * p][0], bb[2 * p][1], bb[2 * p + 1][0], bb[2 * p + 1][1],
                        kbuf + row * 256 + cp * 16);
            }
            #pragma unroll
            for (int j = 0; j < 8; ++j)
                mma_f16(sacc[j], qa[s], bb[j]);
        }

        // ---- causal mask (diagonal tile only) ----
        if (kt == qtile) {
            const int lim_lo = q0 + r_lo - k0;
            const int lim_hi = q0 + r_hi - k0;
            #pragma unroll
            for (int j = 0; j < 8; ++j) {
                int c0 = j * 8 + 2 * t, c1 = c0 + 1;
                if (c0 > lim_lo) sacc[j][0] = -1e30f;
                if (c1 > lim_lo) sacc[j][1] = -1e30f;
                if (c0 > lim_hi) sacc[j][2] = -1e30f;
                if (c1 > lim_hi) sacc[j][3] = -1e30f;
            }
        }

        // ---- online softmax (exp2 domain, half2 exponentials) ----
        float mv_lo = -1e30f, mv_hi = -1e30f;
        #pragma unroll
        for (int j = 0; j < 8; ++j) {
            mv_lo = fmaxf(mv_lo, fmaxf(sacc[j][0], sacc[j][1]));
            mv_hi = fmaxf(mv_hi, fmaxf(sacc[j][2], sacc[j][3]));
        }
        #pragma unroll
        for (int off = 1; off <= 2; off <<= 1) {
            mv_lo = fmaxf(mv_lo, __shfl_xor_sync(0xffffffffu, mv_lo, off));
            mv_hi = fmaxf(mv_hi, __shfl_xor_sync(0xffffffffu, mv_hi, off));
        }
        float mn_lo = fmaxf(m_lo, mv_lo);
        float mn_hi = fmaxf(m_hi, mv_hi);
        float corr_lo = exp2f(m_lo - mn_lo);
        float corr_hi = exp2f(m_hi - mn_hi);
        m_lo = mn_lo; m_hi = mn_hi;

        float ls_lo = 0.f, ls_hi = 0.f;
        uint32_t ph_lo[8], ph_hi[8];
        #pragma unroll
        for (int j = 0; j < 8; ++j) {
            // fp32 subtract, half2 exp2 (one MUFU per pair)
            __half2 s01 = __floats2half2_rn(sacc[j][0] - mn_lo, sacc[j][1] - mn_lo);
            __half2 s23 = __floats2half2_rn(sacc[j][2] - mn_hi, sacc[j][3] - mn_hi);
            uint32_t p01 = ex2_h2(h2u(s01));
            uint32_t p23 = ex2_h2(h2u(s23));
            ph_lo[j] = p01;
            ph_hi[j] = p23;
            float2 f01 = __half22float2(*(__half2*)&p01);
            float2 f23 = __half22float2(*(__half2*)&p23);
            ls_lo += f01.x + f01.y;
            ls_hi += f23.x + f23.y;
        }
        #pragma unroll
        for (int off = 1; off <= 2; off <<= 1) {
            ls_lo += __shfl_xor_sync(0xffffffffu, ls_lo, off);
            ls_hi += __shfl_xor_sync(0xffffffffu, ls_hi, off);
        }
        l_lo = l_lo * corr_lo + ls_lo;
        l_hi = l_hi * corr_hi + ls_hi;

        #pragma unroll
        for (int j = 0; j < 16; ++j) {
            oacc[j][0] *= corr_lo; oacc[j][1] *= corr_lo;
            oacc[j][2] *= corr_hi; oacc[j][3] *= corr_hi;
        }

        // ---- O += P V ----
        #pragma unroll
        for (int s2 = 0; s2 < 4; ++s2) {
            uint32_t a[4] = {ph_lo[2 * s2], ph_hi[2 * s2], ph_lo[2 * s2 + 1], ph_hi[2 * s2 + 1]};
            uint32_t vv[16][2];
            #pragma unroll
            for (int p = 0; p < 8; ++p) {
                int row = p * 16 + lrow;
                int ch  = 2 * s2 + lchq;
                int cp  = ch ^ (row & 7);
                ldsm_x4(vv[2 * p][0], vv[2 * p][1], vv[2 * p + 1][0], vv[2 * p + 1][1],
                        vbuf + row * 128 + cp * 16);
            }
            #pragma unroll
            for (int j = 0; j < 16; ++j)
                mma_f16(oacc[j], a, vv[j]);
        }
        __syncthreads();
    }
#undef PREF

    float inv_lo = 1.0f / l_lo;
    float inv_hi = 1.0f / l_hi;
    __half* o_lo = O + (size_t)(b * S_ + q0 + r_lo) * D_ + h * HD_;
    __half* o_hi = O + (size_t)(b * S_ + q0 + r_hi) * D_ + h * HD_;
    #pragma unroll
    for (int j = 0; j < 16; ++j) {
        int c = j * 8 + 2 * t;
        *(__half2*)(o_lo + c) = __floats2half2_rn(oacc[j][0] * inv_lo, oacc[j][1] * inv_lo);
        *(__half2*)(o_hi + c) = __floats2half2_rn(oacc[j][2] * inv_hi, oacc[j][3] * inv_hi);
    }
}

// =================================================================
extern "C" void kernel_launch(void* const* d_in, const int* in_sizes, int n_in,
                              void* d_out, int out_size) {
    const float* x  = (const float*)d_in[0];
    const float* cs = (const float*)d_in[1];
    const float* sn = (const float*)d_in[2];
    const float* wq = (const float*)d_in[3];
    const float* wk = (const float*)d_in[4];
    const float* wv = (const float*)d_in[5];
    const float* wo = (const float*)d_in[6];
    float* out = (float*)d_out;

    __half *xh, *qh, *kh, *vt, *oh, *wqkvt, *wot;
    cudaGetSymbolAddress((void**)&xh,    g_xh);
    cudaGetSymbolAddress((void**)&qh,    g_qh);
    cudaGetSymbolAddress((void**)&kh,    g_kh);
    cudaGetSymbolAddress((void**)&vt,    g_vt);
    cudaGetSymbolAddress((void**)&oh,    g_oh);
    cudaGetSymbolAddress((void**)&wqkvt, g_wqkvt);
    cudaGetSymbolAddress((void**)&wot,   g_wot);

    cudaFuncSetAttribute(attn_h,    cudaFuncAttributeMaxDynamicSharedMemorySize, ATTN_SMEM);
    cudaFuncSetAttribute(hgemm_qkv, cudaFuncAttributeMaxDynamicSharedMemorySize, HG3_SMEM);
    cudaFuncSetAttribute(hgemm_out, cudaFuncAttributeMaxDynamicSharedMemorySize, HG3_SMEM);

    const int M    = B_ * S_;       // 4096
    const int NQKV = 4096;

    prep_kernel<<<20480, 256>>>(x, wq, wk, wv, wo, xh, wqkvt, wot);

    hgemm_qkv<<<dim3(NQKV / 128, M / 128), 128, HG3_SMEM>>>(xh, wqkvt, cs, sn, qh, kh, vt);

    attn_h<<<dim3(S_ / 64, H_, B_), 128, ATTN_SMEM>>>(qh, kh, vt, oh);

    hgemm_out<<<dim3(D_ / 128, M / 128), 128, HG3_SMEM>>>(oh, wot, out, D_);
}

// round 16
// speedup vs baseline: 1.0355x; 1.0094x over previous
#include <cuda_runtime.h>
#include <cuda_fp16.h>
#include <cstdint>

#define B_   2
#define S_   2048
#define D_   2048
#define H_   16
#define KVH_ 8
#define HD_  128

// ---------------- scratch (no allocations allowed) ----------------
__device__ __half g_xh   [B_ * S_ * D_];
__device__ __half g_qh   [B_ * S_ * D_];
__device__ __half g_kh   [B_ * S_ * KVH_ * HD_];
__device__ __half g_vt   [(KVH_ * HD_) * (B_ * S_)];   // V^T  [1024][4096]
__device__ __half g_oh   [B_ * S_ * D_];
__device__ __half g_wqkvt[(D_ + 2 * KVH_ * HD_) * D_]; // [4096][2048]: wq^T|wk^T|wv^T
__device__ __half g_wot  [D_ * D_];

// ---------------- helpers ----------------
__device__ __forceinline__ void cpa16(uint32_t dst, const void* src) {
    asm volatile("cp.async.cg.shared.global [%0], [%1], 16;" :: "r"(dst), "l"(src));
}
__device__ __forceinline__ void cpa_commit() { asm volatile("cp.async.commit_group;"); }
__device__ __forceinline__ void cpa_wait0()  { asm volatile("cp.async.wait_group 0;"); }
__device__ __forceinline__ void cpa_wait1()  { asm volatile("cp.async.wait_group 1;"); }
__device__ __forceinline__ void mma_f16(float c[4], const uint32_t a[4], const uint32_t b[2]) {
    asm volatile(
        "mma.sync.aligned.m16n8k16.row.col.f32.f16.f16.f32 "
        "{%0,%1,%2,%3}, {%4,%5,%6,%7}, {%8,%9}, {%0,%1,%2,%3};"
        : "+f"(c[0]), "+f"(c[1]), "+f"(c[2]), "+f"(c[3])
        : "r"(a[0]), "r"(a[1]), "r"(a[2]), "r"(a[3]), "r"(b[0]), "r"(b[1]));
}
__device__ __forceinline__ void ldsm_x4(uint32_t& r0, uint32_t& r1, uint32_t& r2, uint32_t& r3,
                                        uint32_t addr) {
    asm volatile("ldmatrix.sync.aligned.m8n8.x4.shared.b16 {%0,%1,%2,%3}, [%4];"
                 : "=r"(r0), "=r"(r1), "=r"(r2), "=r"(r3) : "r"(addr));
}
__device__ __forceinline__ uint32_t smem_u32(const void* p) {
    return (uint32_t)__cvta_generic_to_shared(p);
}
__device__ __forceinline__ uint32_t h2u(__half2 h) { return *(uint32_t*)&h; }
__device__ __forceinline__ uint32_t ex2_h2(uint32_t x) {
    uint32_t r;
    asm("ex2.approx.f16x2 %0, %1;" : "=r"(r) : "r"(x));
    return r;
}

// =================================================================
// Prepass: one launch does x->half AND all 4 weight transposes.
// =================================================================
__global__ void prep_kernel(const float* __restrict__ x,
                            const float* __restrict__ wq, const float* __restrict__ wk,
                            const float* __restrict__ wv, const float* __restrict__ wo,
                            __half* __restrict__ xh,
                            __half* __restrict__ wqkvt, __half* __restrict__ wot) {
    __shared__ float tb[32][33];
    int id = blockIdx.x;
    int tid = threadIdx.x;
    if (id < 8192) {
        int i = id * 256 + tid;
        float4 v = ((const float4*)x)[i];
        __half2 a = __floats2half2_rn(v.x, v.y);
        __half2 b = __floats2half2_rn(v.z, v.w);
        ((uint2*)xh)[i] = make_uint2(h2u(a), h2u(b));
        return;
    }
    id -= 8192;
    const float* W;
    __half* WT;
    int N;
    if (id < 4096)      { W = wq; WT = wqkvt;                           N = 2048; }
    else if (id < 6144) { W = wk; WT = wqkvt + 2048 * 2048; id -= 4096; N = 1024; }
    else if (id < 8192) { W = wv; WT = wqkvt + 3072 * 2048; id -= 6144; N = 1024; }
    else                { W = wo; WT = wot;                 id -= 8192; N = 2048; }
    int nb = N / 32;
    int n0 = (id % nb) * 32, k0 = (id / nb) * 32;
    int tx = tid & 31, ty = tid >> 5;
    #pragma unroll
    for (int i = 0; i < 4; ++i)
        tb[ty + i * 8][tx] = W[(size_t)(k0 + ty + i * 8) * N + n0 + tx];
    __syncthreads();
    #pragma unroll
    for (int i = 0; i < 4; ++i)
        WT[(size_t)(n0 + ty + i * 8) * 2048 + k0 + tx] = __float2half_rn(tb[tx][ty + i * 8]);
}

// =================================================================
// GEMM mainloop (proven R14): 128x128 CTA, 4 warps (2x2 of 64x64),
// BK=64, 2-stage cp.async, ldmatrix, 2 CTAs/SM. 64KB/CTA.
// =================================================================
#define HG3_SMEM 65536

#define GEMM3_MAIN(A_, Bt_, Kdim)                                                       \
    extern __shared__ char smh[];                                                       \
    const uint32_t sbase = smem_u32(smh);                                               \
    const int tid  = threadIdx.x, lane = tid & 31, w = tid >> 5;                        \
    const int g    = lane >> 2, t4 = lane & 3;                                          \
    const int wm   = w >> 1, wn = w & 1;                                                \
    const int bm   = blockIdx.y << 7, bn = blockIdx.x << 7;                             \
    const int sr   = tid >> 3, sc = tid & 7;                                            \
    const __half* aBase = A_ + (size_t)(bm + sr) * (Kdim) + sc * 8;                     \
    const __half* bBase = Bt_ + (size_t)(bn + sr) * (Kdim) + sc * 8;                    \
    const uint32_t sD0 = (uint32_t)(sr * 128 + ((sc ^ (sr & 7)) << 4));                 \
    const int arow0 = wm * 64 + ((lane >> 3) & 1) * 8 + (lane & 7);                     \
    const int achq  = lane >> 4;                                                        \
    const int brow0 = wn * 64 + (lane >> 4) * 8 + (lane & 7);                           \
    const int bchq  = (lane >> 3) & 1;                                                  \
    float acc[4][8][4];                                                                 \
    _Pragma("unroll")                                                                   \
    for (int i = 0; i < 4; ++i)                                                         \
        _Pragma("unroll")                                                               \
        for (int j = 0; j < 8; ++j)                                                     \
            _Pragma("unroll")                                                           \
            for (int r = 0; r < 4; ++r) acc[i][j][r] = 0.f;                             \
    const int ktiles = (Kdim) >> 6;                                                     \
    _Pragma("unroll")                                                                   \
    for (int i = 0; i < 8; ++i) cpa16(sbase + sD0 + i * 2048u, aBase + (size_t)i * 16 * (Kdim)); \
    _Pragma("unroll")                                                                   \
    for (int i = 0; i < 8; ++i) cpa16(sbase + 32768u + sD0 + i * 2048u, bBase + (size_t)i * 16 * (Kdim)); \
    cpa_commit();                                                                       \
    for (int tt = 0; tt < ktiles; ++tt) {                                               \
        if (tt + 1 < ktiles) {                                                          \
            uint32_t ao = ((tt + 1) & 1) * 16384u;                                      \
            uint32_t bo = 32768u + ((tt + 1) & 1) * 16384u;                             \
            const __half* ap = aBase + (size_t)(tt + 1) * 64;                           \
            const __half* bp = bBase + (size_t)(tt + 1) * 64;                           \
            _Pragma("unroll")                                                           \
            for (int i = 0; i < 8; ++i) cpa16(sbase + ao + sD0 + i * 2048u, ap + (size_t)i * 16 * (Kdim)); \
            _Pragma("unroll")                                                           \
            for (int i = 0; i < 8; ++i) cpa16(sbase + bo + sD0 + i * 2048u, bp + (size_t)i * 16 * (Kdim)); \
            cpa_commit();                                                               \
            cpa_wait1();                                                                \
        } else {                                                                        \
            cpa_wait0();                                                                \
        }                                                                               \
        __syncthreads();                                                                \
        const uint32_t sA = sbase + (tt & 1) * 16384u;                                  \
        const uint32_t sB = sbase + 32768u + (tt & 1) * 16384u;                         \
        _Pragma("unroll")                                                               \
        for (int s = 0; s < 4; ++s) {                                                   \
            uint32_t a[4][4], b[8][2];                                                  \
            _Pragma("unroll")                                                           \
            for (int i = 0; i < 4; ++i) {                                               \
                int row = arow0 + i * 16;                                               \
                int ch  = (2 * s + achq) ^ (row & 7);                                   \
                ldsm_x4(a[i][0], a[i][1], a[i][2], a[i][3], sA + row * 128 + (ch << 4)); \
            }                                                                           \
            _Pragma("unroll")                                                           \
            for (int p = 0; p < 4; ++p) {                                               \
                int row = brow0 + p * 16;                                               \
                int ch  = (2 * s + bchq) ^ (row & 7);                                   \
                ldsm_x4(b[2 * p][0], b[2 * p][1], b[2 * p + 1][0], b[2 * p + 1][1],     \
                        sB + row * 128 + (ch << 4));                                    \
            }                                                                           \
            _Pragma("unroll")                                                           \
            for (int i = 0; i < 4; ++i)                                                 \
                _Pragma("unroll")                                                       \
                for (int j = 0; j < 8; ++j)                                             \
                    mma_f16(acc[i][j], a[i], b[j]);                                     \
        }                                                                               \
        __syncthreads();                                                                \
    }

// =================================================================
// Fused QKV projection + RoPE epilogue (Q scaled by log2e/sqrt(HD)).
// =================================================================
__global__ __launch_bounds__(128, 2)
void hgemm_qkv(const __half* __restrict__ A, const __half* __restrict__ Bt,
               const float* __restrict__ cs, const float* __restrict__ sn,
               __half* __restrict__ Qo, __half* __restrict__ Ko, __half* __restrict__ Vt) {
    GEMM3_MAIN(A, Bt, D_)

    const float SCALE2 = 0.12751974007636297f;  // (1/sqrt(128)) * log2(e)
    const int cc = t4 * 2;
    if (bn < D_) {
        #pragma unroll
        for (int i = 0; i < 4; ++i)
            #pragma unroll
            for (int j = 0; j < 8; ++j) {
                int row = bm + wm * 64 + i * 16 + g;
                int col = bn + wn * 64 + j * 8 + cc;
                int dd  = (col & 127) >> 1;
                int s_lo = row & (S_ - 1), s_hi = (row + 8) & (S_ - 1);
                float c0 = cs[s_lo * 64 + dd], si0 = sn[s_lo * 64 + dd];
                float c1 = cs[s_hi * 64 + dd], si1 = sn[s_hi * 64 + dd];
                float r0 = (acc[i][j][0] * c0 - acc[i][j][1] * si0) * SCALE2;
                float r1 = (acc[i][j][0] * si0 + acc[i][j][1] * c0) * SCALE2;
                float r2 = (acc[i][j][2] * c1 - acc[i][j][3] * si1) * SCALE2;
                float r3 = (acc[i][j][2] * si1 + acc[i][j][3] * c1) * SCALE2;
                *(__half2*)(Qo + (size_t)row * D_ + col)       = __floats2half2_rn(r0, r1);
                *(__half2*)(Qo + (size_t)(row + 8) * D_ + col) = __floats2half2_rn(r2, r3);
            }
    } else if (bn < D_ + KVH_ * HD_) {
        #pragma unroll
        for (int i = 0; i < 4; ++i)
            #pragma unroll
            for (int j = 0; j < 8; ++j) {
                int row = bm + wm * 64 + i * 16 + g;
                int col = bn - D_ + wn * 64 + j * 8 + cc;
                int dd  = (col & 127) >> 1;
                int s_lo = row & (S_ - 1), s_hi = (row + 8) & (S_ - 1);
                float c0 = cs[s_lo * 64 + dd], si0 = sn[s_lo * 64 + dd];
                float c1 = cs[s_hi * 64 + dd], si1 = sn[s_hi * 64 + dd];
                float r0 = acc[i][j][0] * c0 - acc[i][j][1] * si0;
                float r1 = acc[i][j][0] * si0 + acc[i][j][1] * c0;
                float r2 = acc[i][j][2] * c1 - acc[i][j][3] * si1;
                float r3 = acc[i][j][2] * si1 + acc[i][j][3] * c1;
                *(__half2*)(Ko + (size_t)row * (KVH_ * HD_) + col)       = __floats2half2_rn(r0, r1);
                *(__half2*)(Ko + (size_t)(row + 8) * (KVH_ * HD_) + col) = __floats2half2_rn(r2, r3);
            }
    } else {
        const int M = B_ * S_;
        #pragma unroll
        for (int i = 0; i < 4; ++i)
            #pragma unroll
            for (int j = 0; j < 8; ++j) {
                int row = bm + wm * 64 + i * 16 + g;
                int col = bn - (D_ + KVH_ * HD_) + wn * 64 + j * 8 + cc;
                Vt[(size_t)col * M + row]           = __float2half_rn(acc[i][j][0]);
                Vt[(size_t)(col + 1) * M + row]     = __float2half_rn(acc[i][j][1]);
                Vt[(size_t)col * M + row + 8]       = __float2half_rn(acc[i][j][2]);
                Vt[(size_t)(col + 1) * M + row + 8] = __float2half_rn(acc[i][j][3]);
            }
    }
}

// =================================================================
// O-projection GEMM: half in, fp32 out.
// =================================================================
__global__ __launch_bounds__(128, 2)
void hgemm_out(const __half* __restrict__ A, const __half* __restrict__ Bt,
               float* __restrict__ Cf, int N) {
    GEMM3_MAIN(A, Bt, D_)
    const int cc = t4 * 2;
    #pragma unroll
    for (int i = 0; i < 4; ++i)
        #pragma unroll
        for (int j = 0; j < 8; ++j) {
            int row = bm + wm * 64 + i * 16 + g;
            int col = bn + wn * 64 + j * 8 + cc;
            *(float2*)(Cf + (size_t)row * N + col)       = make_float2(acc[i][j][0], acc[i][j][1]);
            *(float2*)(Cf + (size_t)(row + 8) * N + col) = make_float2(acc[i][j][2], acc[i][j][3]);
        }
}

// =================================================================
// FP16 flash attention: 64 Q-rows/CTA, 128 threads, 3-stage cp.async,
// ONE __syncthreads per k-tile, ldmatrix, 2 CTAs/SM.
// Softmax exp2-domain with ex2.approx.f16x2.
// smem: 3 stages x (K 16KB + V 16KB) = 96KB/CTA.
// =================================================================
#define ATTN_SMEM 98304

__global__ __launch_bounds__(128, 2)
void attn_h(const __half* __restrict__ Q, const __half* __restrict__ Kg,
            const __half* __restrict__ Vt, __half* __restrict__ O) {
    extern __shared__ char smc[];
    const uint32_t sbase = smem_u32(smc);
    const int tid = threadIdx.x, lane = tid & 31, w = tid >> 5;
    const int g = lane >> 2, t = lane & 3;

    const int qtile = gridDim.x - 1 - blockIdx.x;   // heavy CTAs first
    const int h = blockIdx.y, b = blockIdx.z;
    const int q0 = qtile * 64, kh = h >> 1;
    const int r_lo = w * 16 + g, r_hi = r_lo + 8;

    const int lrow = ((lane >> 4) << 3) + (lane & 7);
    const int lchq = (lane >> 3) & 1;

    const __half* qlo = Q + (size_t)(b * S_ + q0 + r_lo) * D_ + h * HD_;
    const __half* qhi = Q + (size_t)(b * S_ + q0 + r_hi) * D_ + h * HD_;
    uint32_t qa[8][4];
    #pragma unroll
    for (int s = 0; s < 8; ++s) {
        qa[s][0] = *(const uint32_t*)(qlo + s * 16 + 2 * t);
        qa[s][1] = *(const uint32_t*)(qhi + s * 16 + 2 * t);
        qa[s][2] = *(const uint32_t*)(qlo + s * 16 + 2 * t + 8);
        qa[s][3] = *(const uint32_t*)(qhi + s * 16 + 2 * t + 8);
    }

    const __half* kbp = Kg + (size_t)b * S_ * (KVH_ * HD_) + kh * HD_;
    const __half* vtp = Vt + (size_t)(kh * HD_) * (B_ * S_) + b * S_;

    float m_lo = -1e30f, m_hi = -1e30f, l_lo = 0.f, l_hi = 0.f;
    float oacc[16][4];
    #pragma unroll
    for (int j = 0; j < 16; ++j)
        #pragma unroll
        for (int r = 0; r < 4; ++r) oacc[j][r] = 0.f;

    const int nkt = qtile + 1;

    // K: 64 rows x 16 chunks (256B rows); V: 128 rows x 8 chunks (128B rows)
#define PREF(ktp) do {                                                             \
        int k0p = (ktp) * 64;                                                      \
        uint32_t kb2 = sbase + ((ktp) % 3) * 32768u;                               \
        uint32_t vb2 = kb2 + 16384u;                                               \
        _Pragma("unroll")                                                          \
        for (int i = 0; i < 8; ++i) {                                              \
            int idx = tid + i * 128; int r = idx >> 4, c = idx & 15;               \
            int cp = (c & 8) | ((c ^ (r & 7)) & 7);                                \
            cpa16(kb2 + (uint32_t)(r * 256 + cp * 16),                             \
                  kbp + (size_t)(k0p + r) * (KVH_ * HD_) + c * 8);                 \
        }                                                                          \
        _Pragma("unroll")                                                          \
        for (int i = 0; i < 8; ++i) {                                              \
            int idx = tid + i * 128; int d = idx >> 3, c = idx & 7;                \
            int cp = c ^ (d & 7);                                                  \
            cpa16(vb2 + (uint32_t)(d * 128 + cp * 16),                             \
                  vtp + (size_t)d * (B_ * S_) + k0p + c * 8);                      \
        }                                                                          \
        cpa_commit();                                                              \
    } while (0)

    PREF(0);
    if (nkt > 1) PREF(1);

    for (int kt = 0; kt < nkt; ++kt) {
        const int k0 = kt * 64;
        if (kt + 1 < nkt) cpa_wait1(); else cpa_wait0();
        __syncthreads();
        if (kt + 2 < nkt) PREF(kt + 2);

        const uint32_t kbuf = sbase + (kt % 3) * 32768u;
        const uint32_t vbuf = kbuf + 16384u;

        // ---- S = Q K^T (log2 domain) ----
        float sacc[8][4];
        #pragma unroll
        for (int j = 0; j < 8; ++j)
            #pragma unroll
            for (int r = 0; r < 4; ++r) sacc[j][r] = 0.f;

        #pragma unroll
        for (int s = 0; s < 8; ++s) {
            uint32_t bb[8][2];
            #pragma unroll
            for (int p = 0; p < 4; ++p) {
                int row = p * 16 + lrow;
                int ch  = 2 * s + lchq;
                int cp  = (ch & 8) | ((ch ^ (row & 7)) & 7);
                ldsm_x4(bb[2 * p][0], bb[2 * p][1], bb[2 * p + 1][0], bb[2 * p + 1][1],
                        kbuf + row * 256 + cp * 16);
            }
            #pragma unroll
            for (int j = 0; j < 8; ++j)
                mma_f16(sacc[j], qa[s], bb[j]);
        }

        // ---- causal mask (diagonal tile only) ----
        if (kt == qtile) {
            const int lim_lo = q0 + r_lo - k0;
            const int lim_hi = q0 + r_hi - k0;
            #pragma unroll
            for (int j = 0; j < 8; ++j) {
                int c0 = j * 8 + 2 * t, c1 = c0 + 1;
                if (c0 > lim_lo) sacc[j][0] = -1e30f;
                if (c1 > lim_lo) sacc[j][1] = -1e30f;
                if (c0 > lim_hi) sacc[j][2] = -1e30f;
                if (c1 > lim_hi) sacc[j][3] = -1e30f;
            }
        }

        // ---- online softmax (exp2 domain, half2 exponentials) ----
        float mv_lo = -1e30f, mv_hi = -1e30f;
        #pragma unroll
        for (int j = 0; j < 8; ++j) {
            mv_lo = fmaxf(mv_lo, fmaxf(sacc[j][0], sacc[j][1]));
            mv_hi = fmaxf(mv_hi, fmaxf(sacc[j][2], sacc[j][3]));
        }
        #pragma unroll
        for (int off = 1; off <= 2; off <<= 1) {
            mv_lo = fmaxf(mv_lo, __shfl_xor_sync(0xffffffffu, mv_lo, off));
            mv_hi = fmaxf(mv_hi, __shfl_xor_sync(0xffffffffu, mv_hi, off));
        }
        float mn_lo = fmaxf(m_lo, mv_lo);
        float mn_hi = fmaxf(m_hi, mv_hi);
        float corr_lo = exp2f(m_lo - mn_lo);
        float corr_hi = exp2f(m_hi - mn_hi);
        m_lo = mn_lo; m_hi = mn_hi;

        float ls_lo = 0.f, ls_hi = 0.f;
        uint32_t ph_lo[8], ph_hi[8];
        #pragma unroll
        for (int j = 0; j < 8; ++j) {
            __half2 s01 = __floats2half2_rn(sacc[j][0] - mn_lo, sacc[j][1] - mn_lo);
            __half2 s23 = __floats2half2_rn(sacc[j][2] - mn_hi, sacc[j][3] - mn_hi);
            uint32_t p01 = ex2_h2(h2u(s01));
            uint32_t p23 = ex2_h2(h2u(s23));
            ph_lo[j] = p01;
            ph_hi[j] = p23;
            float2 f01 = __half22float2(*(__half2*)&p01);
            float2 f23 = __half22float2(*(__half2*)&p23);
            ls_lo += f01.x + f01.y;
            ls_hi += f23.x + f23.y;
        }
        #pragma unroll
        for (int off = 1; off <= 2; off <<= 1) {
            ls_lo += __shfl_xor_sync(0xffffffffu, ls_lo, off);
            ls_hi += __shfl_xor_sync(0xffffffffu, ls_hi, off);
        }
        l_lo = l_lo * corr_lo + ls_lo;
        l_hi = l_hi * corr_hi + ls_hi;

        #pragma unroll
        for (int j = 0; j < 16; ++j) {
            oacc[j][0] *= corr_lo; oacc[j][1] *= corr_lo;
            oacc[j][2] *= corr_hi; oacc[j][3] *= corr_hi;
        }

        // ---- O += P V ----
        #pragma unroll
        for (int s2 = 0; s2 < 4; ++s2) {
            uint32_t a[4] = {ph_lo[2 * s2], ph_hi[2 * s2], ph_lo[2 * s2 + 1], ph_hi[2 * s2 + 1]};
            uint32_t vv[16][2];
            #pragma unroll
            for (int p = 0; p < 8; ++p) {
                int row = p * 16 + lrow;
                int ch  = 2 * s2 + lchq;
                int cp  = ch ^ (row & 7);
                ldsm_x4(vv[2 * p][0], vv[2 * p][1], vv[2 * p + 1][0], vv[2 * p + 1][1],
                        vbuf + row * 128 + cp * 16);
            }
            #pragma unroll
            for (int j = 0; j < 16; ++j)
                mma_f16(oacc[j], a, vv[j]);
        }
    }
#undef PREF

    float inv_lo = 1.0f / l_lo;
    float inv_hi = 1.0f / l_hi;
    __half* o_lo = O + (size_t)(b * S_ + q0 + r_lo) * D_ + h * HD_;
    __half* o_hi = O + (size_t)(b * S_ + q0 + r_hi) * D_ + h * HD_;
    #pragma unroll
    for (int j = 0; j < 16; ++j) {
        int c = j * 8 + 2 * t;
        *(__half2*)(o_lo + c) = __floats2half2_rn(oacc[j][0] * inv_lo, oacc[j][1] * inv_lo);
        *(__half2*)(o_hi + c) = __floats2half2_rn(oacc[j][2] * inv_hi, oacc[j][3] * inv_hi);
    }
}

// =================================================================
extern "C" void kernel_launch(void* const* d_in, const int* in_sizes, int n_in,
                              void* d_out, int out_size) {
    const float* x  = (const float*)d_in[0];
    const float* cs = (const float*)d_in[1];
    const float* sn = (const float*)d_in[2];
    const float* wq = (const float*)d_in[3];
    const float* wk = (const float*)d_in[4];
    const float* wv = (const float*)d_in[5];
    const float* wo = (const float*)d_in[6];
    float* out = (float*)d_out;

    __half *xh, *qh, *kh, *vt, *oh, *wqkvt, *wot;
    cudaGetSymbolAddress((void**)&xh,    g_xh);
    cudaGetSymbolAddress((void**)&qh,    g_qh);
    cudaGetSymbolAddress((void**)&kh,    g_kh);
    cudaGetSymbolAddress((void**)&vt,    g_vt);
    cudaGetSymbolAddress((void**)&oh,    g_oh);
    cudaGetSymbolAddress((void**)&wqkvt, g_wqkvt);
    cudaGetSymbolAddress((void**)&wot,   g_wot);

    cudaFuncSetAttribute(attn_h,    cudaFuncAttributeMaxDynamicSharedMemorySize, ATTN_SMEM);
    cudaFuncSetAttribute(hgemm_qkv, cudaFuncAttributeMaxDynamicSharedMemorySize, HG3_SMEM);
    cudaFuncSetAttribute(hgemm_out, cudaFuncAttributeMaxDynamicSharedMemorySize, HG3_SMEM);

    const int M    = B_ * S_;       // 4096
    const int NQKV = 4096;

    prep_kernel<<<20480, 256>>>(x, wq, wk, wv, wo, xh, wqkvt, wot);

    hgemm_qkv<<<dim3(NQKV / 128, M / 128), 128, HG3_SMEM>>>(xh, wqkvt, cs, sn, qh, kh, vt);

    attn_h<<<dim3(S_ / 64, H_, B_), 128, ATTN_SMEM>>>(qh, kh, vt, oh);

    hgemm_out<<<dim3(D_ / 128, M / 128), 128, HG3_SMEM>>>(oh, wot, out, D_);
}

// round 17
// speedup vs baseline: 1.0402x; 1.0045x over previous
#include <cuda_runtime.h>
#include <cuda_fp16.h>
#include <cstdint>

#define B_   2
#define S_   2048
#define D_   2048
#define H_   16
#define KVH_ 8
#define HD_  128

// ---------------- scratch (no allocations allowed) ----------------
__device__ __half g_xh   [B_ * S_ * D_];
__device__ __half g_qh   [B_ * S_ * D_];
__device__ __half g_kh   [B_ * S_ * KVH_ * HD_];
__device__ __half g_vt   [(KVH_ * HD_) * (B_ * S_)];   // V^T  [1024][4096]
__device__ __half g_oh   [B_ * S_ * D_];
__device__ __half g_wqkvt[(D_ + 2 * KVH_ * HD_) * D_]; // [4096][2048]: wq^T|wk^T|wv^T
__device__ __half g_wot  [D_ * D_];

// ---------------- helpers ----------------
__device__ __forceinline__ void cpa16(uint32_t dst, const void* src) {
    asm volatile("cp.async.cg.shared.global [%0], [%1], 16;" :: "r"(dst), "l"(src));
}
__device__ __forceinline__ void cpa_commit() { asm volatile("cp.async.commit_group;"); }
__device__ __forceinline__ void cpa_wait0()  { asm volatile("cp.async.wait_group 0;"); }
__device__ __forceinline__ void cpa_wait1()  { asm volatile("cp.async.wait_group 1;"); }
__device__ __forceinline__ void mma_f16(float c[4], const uint32_t a[4], const uint32_t b[2]) {
    asm volatile(
        "mma.sync.aligned.m16n8k16.row.col.f32.f16.f16.f32 "
        "{%0,%1,%2,%3}, {%4,%5,%6,%7}, {%8,%9}, {%0,%1,%2,%3};"
        : "+f"(c[0]), "+f"(c[1]), "+f"(c[2]), "+f"(c[3])
        : "r"(a[0]), "r"(a[1]), "r"(a[2]), "r"(a[3]), "r"(b[0]), "r"(b[1]));
}
__device__ __forceinline__ void ldsm_x4(uint32_t& r0, uint32_t& r1, uint32_t& r2, uint32_t& r3,
                                        uint32_t addr) {
    asm volatile("ldmatrix.sync.aligned.m8n8.x4.shared.b16 {%0,%1,%2,%3}, [%4];"
                 : "=r"(r0), "=r"(r1), "=r"(r2), "=r"(r3) : "r"(addr));
}
__device__ __forceinline__ uint32_t smem_u32(const void* p) {
    return (uint32_t)__cvta_generic_to_shared(p);
}
__device__ __forceinline__ uint32_t h2u(__half2 h) { return *(uint32_t*)&h; }
__device__ __forceinline__ uint32_t ex2_h2(uint32_t x) {
    uint32_t r;
    asm("ex2.approx.f16x2 %0, %1;" : "=r"(r) : "r"(x));
    return r;
}

// =================================================================
// Prepass: one launch does x->half AND all 4 weight transposes.
// =================================================================
__global__ void prep_kernel(const float* __restrict__ x,
                            const float* __restrict__ wq, const float* __restrict__ wk,
                            const float* __restrict__ wv, const float* __restrict__ wo,
                            __half* __restrict__ xh,
                            __half* __restrict__ wqkvt, __half* __restrict__ wot) {
    __shared__ float tb[32][33];
    int id = blockIdx.x;
    int tid = threadIdx.x;
    if (id < 8192) {
        int i = id * 256 + tid;
        float4 v = ((const float4*)x)[i];
        __half2 a = __floats2half2_rn(v.x, v.y);
        __half2 b = __floats2half2_rn(v.z, v.w);
        ((uint2*)xh)[i] = make_uint2(h2u(a), h2u(b));
        return;
    }
    id -= 8192;
    const float* W;
    __half* WT;
    int N;
    if (id < 4096)      { W = wq; WT = wqkvt;                           N = 2048; }
    else if (id < 6144) { W = wk; WT = wqkvt + 2048 * 2048; id -= 4096; N = 1024; }
    else if (id < 8192) { W = wv; WT = wqkvt + 3072 * 2048; id -= 6144; N = 1024; }
    else                { W = wo; WT = wot;                 id -= 8192; N = 2048; }
    int nb = N / 32;
    int n0 = (id % nb) * 32, k0 = (id / nb) * 32;
    int tx = tid & 31, ty = tid >> 5;
    #pragma unroll
    for (int i = 0; i < 4; ++i)
        tb[ty + i * 8][tx] = W[(size_t)(k0 + ty + i * 8) * N + n0 + tx];
    __syncthreads();
    #pragma unroll
    for (int i = 0; i < 4; ++i)
        WT[(size_t)(n0 + ty + i * 8) * 2048 + k0 + tx] = __float2half_rn(tb[tx][ty + i * 8]);
}

// =================================================================
// GEMM mainloop v6: 128x128 CTA, 4 warps (2x2 of 64x64), BK=64,
// 2-stage cp.async, ldmatrix with EXPLICIT fragment double-buffering
// (load s+1 frags before the s mma wall), 2 CTAs/SM. 64KB/CTA.
// =================================================================
#define HG3_SMEM 65536

#define LDFRAG(buf, s)                                                                  \
    do {                                                                                \
        _Pragma("unroll")                                                               \
        for (int i = 0; i < 4; ++i) {                                                   \
            int row = arow0 + i * 16;                                                   \
            int ch  = (2 * (s) + achq) ^ (row & 7);                                     \
            ldsm_x4(a[buf][i][0], a[buf][i][1], a[buf][i][2], a[buf][i][3],             \
                    sA + row * 128 + (ch << 4));                                        \
        }                                                                               \
        _Pragma("unroll")                                                               \
        for (int p = 0; p < 4; ++p) {                                                   \
            int row = brow0 + p * 16;                                                   \
            int ch  = (2 * (s) + bchq) ^ (row & 7);                                     \
            ldsm_x4(b[buf][2 * p][0], b[buf][2 * p][1],                                 \
                    b[buf][2 * p + 1][0], b[buf][2 * p + 1][1],                         \
                    sB + row * 128 + (ch << 4));                                        \
        }                                                                               \
    } while (0)

#define GEMM3_MAIN(A_, Bt_, Kdim)                                                       \
    extern __shared__ char smh[];                                                       \
    const uint32_t sbase = smem_u32(smh);                                               \
    const int tid  = threadIdx.x, lane = tid & 31, w = tid >> 5;                        \
    const int g    = lane >> 2, t4 = lane & 3;                                          \
    const int wm   = w >> 1, wn = w & 1;                                                \
    const int bm   = blockIdx.y << 7, bn = blockIdx.x << 7;                             \
    const int sr   = tid >> 3, sc = tid & 7;                                            \
    const __half* aBase = A_ + (size_t)(bm + sr) * (Kdim) + sc * 8;                     \
    const __half* bBase = Bt_ + (size_t)(bn + sr) * (Kdim) + sc * 8;                    \
    const uint32_t sD0 = (uint32_t)(sr * 128 + ((sc ^ (sr & 7)) << 4));                 \
    const int arow0 = wm * 64 + ((lane >> 3) & 1) * 8 + (lane & 7);                     \
    const int achq  = lane >> 4;                                                        \
    const int brow0 = wn * 64 + (lane >> 4) * 8 + (lane & 7);                           \
    const int bchq  = (lane >> 3) & 1;                                                  \
    float acc[4][8][4];                                                                 \
    _Pragma("unroll")                                                                   \
    for (int i = 0; i < 4; ++i)                                                         \
        _Pragma("unroll")                                                               \
        for (int j = 0; j < 8; ++j)                                                     \
            _Pragma("unroll")                                                           \
            for (int r = 0; r < 4; ++r) acc[i][j][r] = 0.f;                             \
    const int ktiles = (Kdim) >> 6;                                                     \
    _Pragma("unroll")                                                                   \
    for (int i = 0; i < 8; ++i) cpa16(sbase + sD0 + i * 2048u, aBase + (size_t)i * 16 * (Kdim)); \
    _Pragma("unroll")                                                                   \
    for (int i = 0; i < 8; ++i) cpa16(sbase + 32768u + sD0 + i * 2048u, bBase + (size_t)i * 16 * (Kdim)); \
    cpa_commit();                                                                       \
    for (int tt = 0; tt < ktiles; ++tt) {                                               \
        if (tt + 1 < ktiles) {                                                          \
            uint32_t ao = ((tt + 1) & 1) * 16384u;                                      \
            uint32_t bo = 32768u + ((tt + 1) & 1) * 16384u;                             \
            const __half* ap = aBase + (size_t)(tt + 1) * 64;                           \
            const __half* bp = bBase + (size_t)(tt + 1) * 64;                           \
            _Pragma("unroll")                                                           \
            for (int i = 0; i < 8; ++i) cpa16(sbase + ao + sD0 + i * 2048u, ap + (size_t)i * 16 * (Kdim)); \
            _Pragma("unroll")                                                           \
            for (int i = 0; i < 8; ++i) cpa16(sbase + bo + sD0 + i * 2048u, bp + (size_t)i * 16 * (Kdim)); \
            cpa_commit();                                                               \
            cpa_wait1();                                                                \
        } else {                                                                        \
            cpa_wait0();                                                                \
        }                                                                               \
        __syncthreads();                                                                \
        const uint32_t sA = sbase + (tt & 1) * 16384u;                                  \
        const uint32_t sB = sbase + 32768u + (tt & 1) * 16384u;                         \
        uint32_t a[2][4][4], b[2][8][2];                                                \
        LDFRAG(0, 0);                                                                   \
        _Pragma("unroll")                                                               \
        for (int s = 0; s < 4; ++s) {                                                   \
            const int cur = s & 1;                                                      \
            if (s < 3) LDFRAG(cur ^ 1, s + 1);                                          \
            _Pragma("unroll")                                                           \
            for (int i = 0; i < 4; ++i)                                                 \
                _Pragma("unroll")                                                       \
                for (int j = 0; j < 8; ++j)                                             \
                    mma_f16(acc[i][j], a[cur][i], b[cur][j]);                           \
        }                                                                               \
        __syncthreads();                                                                \
    }

// =================================================================
// Fused QKV projection + RoPE epilogue (Q scaled by log2e/sqrt(HD)).
// =================================================================
__global__ __launch_bounds__(128, 2)
void hgemm_qkv(const __half* __restrict__ A, const __half* __restrict__ Bt,
               const float* __restrict__ cs, const float* __restrict__ sn,
               __half* __restrict__ Qo, __half* __restrict__ Ko, __half* __restrict__ Vt) {
    GEMM3_MAIN(A, Bt, D_)

    const float SCALE2 = 0.12751974007636297f;  // (1/sqrt(128)) * log2(e)
    const int cc = t4 * 2;
    if (bn < D_) {
        #pragma unroll
        for (int i = 0; i < 4; ++i)
            #pragma unroll
            for (int j = 0; j < 8; ++j) {
                int row = bm + wm * 64 + i * 16 + g;
                int col = bn + wn * 64 + j * 8 + cc;
                int dd  = (col & 127) >> 1;
                int s_lo = row & (S_ - 1), s_hi = (row + 8) & (S_ - 1);
                float c0 = cs[s_lo * 64 + dd], si0 = sn[s_lo * 64 + dd];
                float c1 = cs[s_hi * 64 + dd], si1 = sn[s_hi * 64 + dd];
                float r0 = (acc[i][j][0] * c0 - acc[i][j][1] * si0) * SCALE2;
                float r1 = (acc[i][j][0] * si0 + acc[i][j][1] * c0) * SCALE2;
                float r2 = (acc[i][j][2] * c1 - acc[i][j][3] * si1) * SCALE2;
                float r3 = (acc[i][j][2] * si1 + acc[i][j][3] * c1) * SCALE2;
                *(__half2*)(Qo + (size_t)row * D_ + col)       = __floats2half2_rn(r0, r1);
                *(__half2*)(Qo + (size_t)(row + 8) * D_ + col) = __floats2half2_rn(r2, r3);
            }
    } else if (bn < D_ + KVH_ * HD_) {
        #pragma unroll
        for (int i = 0; i < 4; ++i)
            #pragma unroll
            for (int j = 0; j < 8; ++j) {
                int row = bm + wm * 64 + i * 16 + g;
                int col = bn - D_ + wn * 64 + j * 8 + cc;
                int dd  = (col & 127) >> 1;
                int s_lo = row & (S_ - 1), s_hi = (row + 8) & (S_ - 1);
                float c0 = cs[s_lo * 64 + dd], si0 = sn[s_lo * 64 + dd];
                float c1 = cs[s_hi * 64 + dd], si1 = sn[s_hi * 64 + dd];
                float r0 = acc[i][j][0] * c0 - acc[i][j][1] * si0;
                float r1 = acc[i][j][0] * si0 + acc[i][j][1] * c0;
                float r2 = acc[i][j][2] * c1 - acc[i][j][3] * si1;
                float r3 = acc[i][j][2] * si1 + acc[i][j][3] * c1;
                *(__half2*)(Ko + (size_t)row * (KVH_ * HD_) + col)       = __floats2half2_rn(r0, r1);
                *(__half2*)(Ko + (size_t)(row + 8) * (KVH_ * HD_) + col) = __floats2half2_rn(r2, r3);
            }
    } else {
        const int M = B_ * S_;
        #pragma unroll
        for (int i = 0; i < 4; ++i)
            #pragma unroll
            for (int j = 0; j < 8; ++j) {
                int row = bm + wm * 64 + i * 16 + g;
                int col = bn - (D_ + KVH_ * HD_) + wn * 64 + j * 8 + cc;
                Vt[(size_t)col * M + row]           = __float2half_rn(acc[i][j][0]);
                Vt[(size_t)(col + 1) * M + row]     = __float2half_rn(acc[i][j][1]);
                Vt[(size_t)col * M + row + 8]       = __float2half_rn(acc[i][j][2]);
                Vt[(size_t)(col + 1) * M + row + 8] = __float2half_rn(acc[i][j][3]);
            }
    }
}

// =================================================================
// O-projection GEMM: half in, fp32 out.
// =================================================================
__global__ __launch_bounds__(128, 2)
void hgemm_out(const __half* __restrict__ A, const __half* __restrict__ Bt,
               float* __restrict__ Cf, int N) {
    GEMM3_MAIN(A, Bt, D_)
    const int cc = t4 * 2;
    #pragma unroll
    for (int i = 0; i < 4; ++i)
        #pragma unroll
        for (int j = 0; j < 8; ++j) {
            int row = bm + wm * 64 + i * 16 + g;
            int col = bn + wn * 64 + j * 8 + cc;
            *(float2*)(Cf + (size_t)row * N + col)       = make_float2(acc[i][j][0], acc[i][j][1]);
            *(float2*)(Cf + (size_t)(row + 8) * N + col) = make_float2(acc[i][j][2], acc[i][j][3]);
        }
}

// =================================================================
// FP16 flash attention (R16 proven): 64 Q-rows/CTA, 128 threads,
// 3-stage cp.async, ONE sync per k-tile, ldmatrix, 2 CTAs/SM,
// exp2-domain softmax with ex2.approx.f16x2. 96KB/CTA.
// =================================================================
#define ATTN_SMEM 98304

__global__ __launch_bounds__(128, 2)
void attn_h(const __half* __restrict__ Q, const __half* __restrict__ Kg,
            const __half* __restrict__ Vt, __half* __restrict__ O) {
    extern __shared__ char smc[];
    const uint32_t sbase = smem_u32(smc);
    const int tid = threadIdx.x, lane = tid & 31, w = tid >> 5;
    const int g = lane >> 2, t = lane & 3;

    const int qtile = gridDim.x - 1 - blockIdx.x;   // heavy CTAs first
    const int h = blockIdx.y, b = blockIdx.z;
    const int q0 = qtile * 64, kh = h >> 1;
    const int r_lo = w * 16 + g, r_hi = r_lo + 8;

    const int lrow = ((lane >> 4) << 3) + (lane & 7);
    const int lchq = (lane >> 3) & 1;

    const __half* qlo = Q + (size_t)(b * S_ + q0 + r_lo) * D_ + h * HD_;
    const __half* qhi = Q + (size_t)(b * S_ + q0 + r_hi) * D_ + h * HD_;
    uint32_t qa[8][4];
    #pragma unroll
    for (int s = 0; s < 8; ++s) {
        qa[s][0] = *(const uint32_t*)(qlo + s * 16 + 2 * t);
        qa[s][1] = *(const uint32_t*)(qhi + s * 16 + 2 * t);
        qa[s][2] = *(const uint32_t*)(qlo + s * 16 + 2 * t + 8);
        qa[s][3] = *(const uint32_t*)(qhi + s * 16 + 2 * t + 8);
    }

    const __half* kbp = Kg + (size_t)b * S_ * (KVH_ * HD_) + kh * HD_;
    const __half* vtp = Vt + (size_t)(kh * HD_) * (B_ * S_) + b * S_;

    float m_lo = -1e30f, m_hi = -1e30f, l_lo = 0.f, l_hi = 0.f;
    float oacc[16][4];
    #pragma unroll
    for (int j = 0; j < 16; ++j)
        #pragma unroll
        for (int r = 0; r < 4; ++r) oacc[j][r] = 0.f;

    const int nkt = qtile + 1;

#define PREF(ktp) do {                                                             \
        int k0p = (ktp) * 64;                                                      \
        uint32_t kb2 = sbase + ((ktp) % 3) * 32768u;                               \
        uint32_t vb2 = kb2 + 16384u;                                               \
        _Pragma("unroll")                                                          \
        for (int i = 0; i < 8; ++i) {                                              \
            int idx = tid + i * 128; int r = idx >> 4, c = idx & 15;               \
            int cp = (c & 8) | ((c ^ (r & 7)) & 7);                                \
            cpa16(kb2 + (uint32_t)(r * 256 + cp * 16),                             \
                  kbp + (size_t)(k0p + r) * (KVH_ * HD_) + c * 8);                 \
        }                                                                          \
        _Pragma("unroll")                                                          \
        for (int i = 0; i < 8; ++i) {                                              \
            int idx = tid + i * 128; int d = idx >> 3, c = idx & 7;                \
            int cp = c ^ (d & 7);                                                  \
            cpa16(vb2 + (uint32_t)(d * 128 + cp * 16),                             \
                  vtp + (size_t)d * (B_ * S_) + k0p + c * 8);                      \
        }                                                                          \
        cpa_commit();                                                              \
    } while (0)

    PREF(0);
    if (nkt > 1) PREF(1);

    for (int kt = 0; kt < nkt; ++kt) {
        const int k0 = kt * 64;
        if (kt + 1 < nkt) cpa_wait1(); else cpa_wait0();
        __syncthreads();
        if (kt + 2 < nkt) PREF(kt + 2);

        const uint32_t kbuf = sbase + (kt % 3) * 32768u;
        const uint32_t vbuf = kbuf + 16384u;

        // ---- S = Q K^T (log2 domain) ----
        float sacc[8][4];
        #pragma unroll
        for (int j = 0; j < 8; ++j)
            #pragma unroll
            for (int r = 0; r < 4; ++r) sacc[j][r] = 0.f;

        #pragma unroll
        for (int s = 0; s < 8; ++s) {
            uint32_t bb[8][2];
            #pragma unroll
            for (int p = 0; p < 4; ++p) {
                int row = p * 16 + lrow;
                int ch  = 2 * s + lchq;
                int cp  = (ch & 8) | ((ch ^ (row & 7)) & 7);
                ldsm_x4(bb[2 * p][0], bb[2 * p][1], bb[2 * p + 1][0], bb[2 * p + 1][1],
                        kbuf + row * 256 + cp * 16);
            }
            #pragma unroll
            for (int j = 0; j < 8; ++j)
                mma_f16(sacc[j], qa[s], bb[j]);
        }

        // ---- causal mask (diagonal tile only) ----
        if (kt == qtile) {
            const int lim_lo = q0 + r_lo - k0;
            const int lim_hi = q0 + r_hi - k0;
            #pragma unroll
            for (int j = 0; j < 8; ++j) {
                int c0 = j * 8 + 2 * t, c1 = c0 + 1;
                if (c0 > lim_lo) sacc[j][0] = -1e30f;
                if (c1 > lim_lo) sacc[j][1] = -1e30f;
                if (c0 > lim_hi) sacc[j][2] = -1e30f;
                if (c1 > lim_hi) sacc[j][3] = -1e30f;
            }
        }

        // ---- online softmax (exp2 domain, half2 exponentials) ----
        float mv_lo = -1e30f, mv_hi = -1e30f;
        #pragma unroll
        for (int j = 0; j < 8; ++j) {
            mv_lo = fmaxf(mv_lo, fmaxf(sacc[j][0], sacc[j][1]));
            mv_hi = fmaxf(mv_hi, fmaxf(sacc[j][2], sacc[j][3]));
        }
        #pragma unroll
        for (int off = 1; off <= 2; off <<= 1) {
            mv_lo = fmaxf(mv_lo, __shfl_xor_sync(0xffffffffu, mv_lo, off));
            mv_hi = fmaxf(mv_hi, __shfl_xor_sync(0xffffffffu, mv_hi, off));
        }
        float mn_lo = fmaxf(m_lo, mv_lo);
        float mn_hi = fmaxf(m_hi, mv_hi);
        float corr_lo = exp2f(m_lo - mn_lo);
        float corr_hi = exp2f(m_hi - mn_hi);
        m_lo = mn_lo; m_hi = mn_hi;

        float ls_lo = 0.f, ls_hi = 0.f;
        uint32_t ph_lo[8], ph_hi[8];
        #pragma unroll
        for (int j = 0; j < 8; ++j) {
            __half2 s01 = __floats2half2_rn(sacc[j][0] - mn_lo, sacc[j][1] - mn_lo);
            __half2 s23 = __floats2half2_rn(sacc[j][2] - mn_hi, sacc[j][3] - mn_hi);
            uint32_t p01 = ex2_h2(h2u(s01));
            uint32_t p23 = ex2_h2(h2u(s23));
            ph_lo[j] = p01;
            ph_hi[j] = p23;
            float2 f01 = __half22float2(*(__half2*)&p01);
            float2 f23 = __half22float2(*(__half2*)&p23);
            ls_lo += f01.x + f01.y;
            ls_hi += f23.x + f23.y;
        }
        #pragma unroll
        for (int off = 1; off <= 2; off <<= 1) {
            ls_lo += __shfl_xor_sync(0xffffffffu, ls_lo, off);
            ls_hi += __shfl_xor_sync(0xffffffffu, ls_hi, off);
        }
        l_lo = l_lo * corr_lo + ls_lo;
        l_hi = l_hi * corr_hi + ls_hi;

        #pragma unroll
        for (int j = 0; j < 16; ++j) {
            oacc[j][0] *= corr_lo; oacc[j][1] *= corr_lo;
            oacc[j][2] *= corr_hi; oacc[j][3] *= corr_hi;
        }

        // ---- O += P V ----
        #pragma unroll
        for (int s2 = 0; s2 < 4; ++s2) {
            uint32_t a[4] = {ph_lo[2 * s2], ph_hi[2 * s2], ph_lo[2 * s2 + 1], ph_hi[2 * s2 + 1]};
            uint32_t vv[16][2];
            #pragma unroll
            for (int p = 0; p < 8; ++p) {
                int row = p * 16 + lrow;
                int ch  = 2 * s2 + lchq;
                int cp  = ch ^ (row & 7);
                ldsm_x4(vv[2 * p][0], vv[2 * p][1], vv[2 * p + 1][0], vv[2 * p + 1][1],
                        vbuf + row * 128 + cp * 16);
            }
            #pragma unroll
            for (int j = 0; j < 16; ++j)
                mma_f16(oacc[j], a, vv[j]);
        }
    }
#undef PREF

    float inv_lo = 1.0f / l_lo;
    float inv_hi = 1.0f / l_hi;
    __half* o_lo = O + (size_t)(b * S_ + q0 + r_lo) * D_ + h * HD_;
    __half* o_hi = O + (size_t)(b * S_ + q0 + r_hi) * D_ + h * HD_;
    #pragma unroll
    for (int j = 0; j < 16; ++j) {
        int c = j * 8 + 2 * t;
        *(__half2*)(o_lo + c) = __floats2half2_rn(oacc[j][0] * inv_lo, oacc[j][1] * inv_lo);
        *(__half2*)(o_hi + c) = __floats2half2_rn(oacc[j][2] * inv_hi, oacc[j][3] * inv_hi);
    }
}

// =================================================================
extern "C" void kernel_launch(void* const* d_in, const int* in_sizes, int n_in,
                              void* d_out, int out_size) {
    const float* x  = (const float*)d_in[0];
    const float* cs = (const float*)d_in[1];
    const float* sn = (const float*)d_in[2];
    const float* wq = (const float*)d_in[3];
    const float* wk = (const float*)d_in[4];
    const float* wv = (const float*)d_in[5];
    const float* wo = (const float*)d_in[6];
    float* out = (float*)d_out;

    __half *xh, *qh, *kh, *vt, *oh, *wqkvt, *wot;
    cudaGetSymbolAddress((void**)&xh,    g_xh);
    cudaGetSymbolAddress((void**)&qh,    g_qh);
    cudaGetSymbolAddress((void**)&kh,    g_kh);
    cudaGetSymbolAddress((void**)&vt,    g_vt);
    cudaGetSymbolAddress((void**)&oh,    g_oh);
    cudaGetSymbolAddress((void**)&wqkvt, g_wqkvt);
    cudaGetSymbolAddress((void**)&wot,   g_wot);

    cudaFuncSetAttribute(attn_h,    cudaFuncAttributeMaxDynamicSharedMemorySize, ATTN_SMEM);
    cudaFuncSetAttribute(hgemm_qkv, cudaFuncAttributeMaxDynamicSharedMemorySize, HG3_SMEM);
    cudaFuncSetAttribute(hgemm_out, cudaFuncAttributeMaxDynamicSharedMemorySize, HG3_SMEM);

    const int M    = B_ * S_;       // 4096
    const int NQKV = 4096;

    prep_kernel<<<20480, 256>>>(x, wq, wk, wv, wo, xh, wqkvt, wot);

    hgemm_qkv<<<dim3(NQKV / 128, M / 128), 128, HG3_SMEM>>>(xh, wqkvt, cs, sn, qh, kh, vt);

    attn_h<<<dim3(S_ / 64, H_, B_), 128, ATTN_SMEM>>>(qh, kh, vt, oh);

    hgemm_out<<<dim3(D_ / 128, M / 128), 128, HG3_SMEM>>>(oh, wot, out, D_);
}